// round 13
// baseline (speedup 1.0000x reference)
#include <cuda_runtime.h>
#include <cstdint>
#include <math.h>

#define NNODES 4096
#define HIDD   256
#define NHEADS 8
#define NEDGE  65536
#define NDIR   (2*NEDGE)

__device__ float d_x   [NNODES*HIDD];
__device__ float d_qkv [NNODES*3*HIDD];
__device__ float d_att [NNODES*HIDD];
__device__ float d_x2  [NNODES*HIDD];
__device__ float d_s1  [NNODES*HIDD];
__device__ float d_g1  [NNODES*HIDD];
__device__ float d_s2  [NNODES*HIDD];
__device__ float d_g2  [NNODES*128];
__device__ float d_deg [NNODES];
__device__ float d_dinv[NNODES];
__device__ int   d_rowcnt[NNODES];
__device__ int   d_fillcnt[NNODES];
__device__ int   d_rowptr[NNODES+1];
__device__ int   d_col [NDIR];
__device__ float d_coef[NDIR];
__device__ int   d_e64flag;
__device__ float d_wq[768*256];
__device__ float d_wp[256*256];
__device__ float d_w1[256*256];
__device__ float d_w2[128*256];
__device__ float d_ws[128*256];
__device__ float d_wc[256*256];

__device__ __forceinline__ unsigned f2tf(float x) {
    unsigned r; asm("cvt.rna.tf32.f32 %0, %1;" : "=r"(r) : "f"(x)); return r;
}
__device__ __forceinline__ float tfr(float x) { return __uint_as_float(f2tf(x)); }
__device__ __forceinline__ unsigned F2U(float x) { return __float_as_uint(x); }
__device__ __forceinline__ void mma8(float* d, const unsigned* a, const unsigned* b) {
    asm volatile("mma.sync.aligned.m16n8k8.row.col.f32.tf32.tf32.f32 "
        "{%0,%1,%2,%3}, {%4,%5,%6,%7}, {%8,%9}, {%0,%1,%2,%3};"
        : "+f"(d[0]), "+f"(d[1]), "+f"(d[2]), "+f"(d[3])
        : "r"(a[0]), "r"(a[1]), "r"(a[2]), "r"(a[3]), "r"(b[0]), "r"(b[1]));
}
__device__ __forceinline__ void cpa16(unsigned dst, const float* src) {
    asm volatile("cp.async.cg.shared.global [%0], [%1], 16;" :: "r"(dst), "l"(src));
}
__device__ __forceinline__ void cpa_commit() { asm volatile("cp.async.commit_group;"); }
__device__ __forceinline__ void cpa_wait1()  { asm volatile("cp.async.wait_group 1;"); }
__device__ __forceinline__ void cpa_wait0()  { asm volatile("cp.async.wait_group 0;"); }
__device__ __forceinline__ unsigned smem_u32(const void* p) {
    return (unsigned)__cvta_generic_to_shared(p);
}

// ---- misc ----
__global__ void k_init(const int* __restrict__ e) {
    int i = blockIdx.x*256 + threadIdx.x;
    if (i < NNODES) { d_deg[i]=0.f; d_rowcnt[i]=0; d_fillcnt[i]=0; }
    if (blockIdx.x == 0 && threadIdx.x == 0) {
        int z = 0;
        #pragma unroll
        for (int j = 1; j < 16; j += 2) z |= e[j];
        d_e64flag = (z == 0) ? 1 : 0;
    }
}
#define RW_TOT 458752
__global__ void k_round_all(const float* __restrict__ qw, const float* __restrict__ pw,
                            const float* __restrict__ w1, const float* __restrict__ w2,
                            const float* __restrict__ sw, const float* __restrict__ cw) {
    int j = blockIdx.x*256 + threadIdx.x;
    if (j >= RW_TOT) return;
    if (j < 196608) { d_wq[j] = tfr(qw[j]); return; }  j -= 196608;
    if (j < 65536)  { d_wp[j] = tfr(pw[j]); return; }  j -= 65536;
    if (j < 65536)  { d_w1[j] = tfr(w1[j]); return; }  j -= 65536;
    if (j < 32768)  { d_w2[j] = tfr(w2[j]); return; }  j -= 32768;
    if (j < 32768)  { d_ws[j] = tfr(sw[j]); return; }  j -= 32768;
    d_wc[j] = tfr(cw[j]);
}
__device__ __forceinline__ void get_edge(const void* edges, int e, int& r, int& c) {
    if (d_e64flag) { const long long* p = (const long long*)edges; r = (int)p[2*e]; c = (int)p[2*e+1]; }
    else           { const int* p = (const int*)edges;             r = p[2*e];      c = p[2*e+1]; }
}

// ---- tf32 GEMM: C[M,N] = A[M,256] @ B[N,256]^T + bias (+resid) (+LN+ReLU) --
// block tile (MT*32) x BN, 8 warps (2 x 4), warp tile (MT*16) x (BN/4).
// LN=true requires BN == N (full row in one block).
template<int MT, int BN, bool RND, bool LN>
__global__ __launch_bounds__(256,2) void k_gemm_t(
    const float* __restrict__ A, const float* __restrict__ B,
    const float* __restrict__ bias, const float* __restrict__ resid,
    const float* __restrict__ lnG, const float* __restrict__ lnB,
    float* __restrict__ C, int N)
{
    extern __shared__ float fs[];
    const int BM  = MT*32;
    const int NT  = BN/32;            // n-frags per warp
    const int ASZ = BM*36;
    const int STG = ASZ + BN*36;
    const int NST = (BN == 256) ? 2 : 3;
    unsigned sbase = smem_u32(fs);
    const int K = 256;
    int m0 = blockIdx.y*BM, n0 = blockIdx.x*BN;
    int tid = threadIdx.x;
    int warp = tid >> 5, lane = tid & 31;
    int wy = warp >> 2, wx = warp & 3;
    int g = lane >> 2, t = lane & 3;
    float acc[MT][NT][4] = {};
    int lr = tid >> 3, lkv = (tid & 7)*4;

    auto issue = [&](int k0, int st) {
        #pragma unroll
        for (int j = 0; j < MT; j++) {
            int r = lr + j*32;
            cpa16(sbase + (st*STG + r*36 + lkv)*4, &A[(size_t)(m0+r)*K + k0 + lkv]);
        }
        #pragma unroll
        for (int j = 0; j < BN/32; j++) {
            int r = lr + j*32;
            cpa16(sbase + (st*STG + ASZ + r*36 + lkv)*4, &B[(size_t)(n0+r)*K + k0 + lkv]);
        }
        cpa_commit();
    };

    issue(0, 0);
    if (NST == 3) issue(32, 1);
    for (int i = 0; i < 8; i++) {
        if (NST == 3) { if (i < 7) cpa_wait1(); else cpa_wait0(); }
        else cpa_wait0();
        __syncthreads();
        if (i < 8 - (NST-1)) issue((i+NST-1)*32, (i+NST-1)%NST);
        const float* sA = fs + (i%NST)*STG;
        const float* sB = sA + ASZ;
        #pragma unroll
        for (int kc = 0; kc < 4; kc++) {
            unsigned a[MT][4], b[NT][2];
            #pragma unroll
            for (int mt = 0; mt < MT; mt++) {
                int r = wy*(16*MT) + mt*16 + g;
                a[mt][0] = F2U(sA[r*36 + kc*8 + t]);
                a[mt][1] = F2U(sA[(r+8)*36 + kc*8 + t]);
                a[mt][2] = F2U(sA[r*36 + kc*8 + t + 4]);
                a[mt][3] = F2U(sA[(r+8)*36 + kc*8 + t + 4]);
            }
            #pragma unroll
            for (int nt = 0; nt < NT; nt++) {
                int r = wx*(8*NT) + nt*8 + g;
                b[nt][0] = F2U(sB[r*36 + kc*8 + t]);
                b[nt][1] = F2U(sB[r*36 + kc*8 + t + 4]);
            }
            #pragma unroll
            for (int mt = 0; mt < MT; mt++)
                #pragma unroll
                for (int nt = 0; nt < NT; nt++)
                    mma8(acc[mt][nt], a[mt], b[nt]);
        }
        __syncthreads();
    }

    if (LN) {
        // add bias, per-row LayerNorm + ReLU over the full BN-wide row
        float* redS = fs;
        float* redQ = fs + BM*4;
        #pragma unroll
        for (int mt = 0; mt < MT; mt++) {
            float sl = 0.f, ql = 0.f, sh = 0.f, qh = 0.f;
            #pragma unroll
            for (int nt = 0; nt < NT; nt++) {
                int col = n0 + wx*(8*NT) + nt*8 + t*2;
                float2 bi = *(const float2*)&bias[col];
                float v0 = acc[mt][nt][0]+bi.x, v1 = acc[mt][nt][1]+bi.y;
                float w0 = acc[mt][nt][2]+bi.x, w1 = acc[mt][nt][3]+bi.y;
                acc[mt][nt][0]=v0; acc[mt][nt][1]=v1; acc[mt][nt][2]=w0; acc[mt][nt][3]=w1;
                sl += v0+v1; ql += v0*v0+v1*v1;
                sh += w0+w1; qh += w0*w0+w1*w1;
            }
            #pragma unroll
            for (int msk = 1; msk < 4; msk <<= 1) {
                sl += __shfl_xor_sync(0xffffffffu, sl, msk);
                ql += __shfl_xor_sync(0xffffffffu, ql, msk);
                sh += __shfl_xor_sync(0xffffffffu, sh, msk);
                qh += __shfl_xor_sync(0xffffffffu, qh, msk);
            }
            if (t == 0) {
                int rl = wy*(16*MT) + mt*16 + g;
                redS[rl*4 + wx] = sl;     redQ[rl*4 + wx] = ql;
                redS[(rl+8)*4 + wx] = sh; redQ[(rl+8)*4 + wx] = qh;
            }
        }
        __syncthreads();
        #pragma unroll
        for (int mt = 0; mt < MT; mt++) {
            int rl = wy*(16*MT) + mt*16 + g;
            float S0 = redS[rl*4]+redS[rl*4+1]+redS[rl*4+2]+redS[rl*4+3];
            float Q0 = redQ[rl*4]+redQ[rl*4+1]+redQ[rl*4+2]+redQ[rl*4+3];
            float S1 = redS[(rl+8)*4]+redS[(rl+8)*4+1]+redS[(rl+8)*4+2]+redS[(rl+8)*4+3];
            float Q1 = redQ[(rl+8)*4]+redQ[(rl+8)*4+1]+redQ[(rl+8)*4+2]+redQ[(rl+8)*4+3];
            float mu0 = S0/BN, r0v = rsqrtf(Q0/BN - mu0*mu0 + 1e-5f);
            float mu1 = S1/BN, r1v = rsqrtf(Q1/BN - mu1*mu1 + 1e-5f);
            int row = m0 + rl;
            #pragma unroll
            for (int nt = 0; nt < NT; nt++) {
                int col = n0 + wx*(8*NT) + nt*8 + t*2;
                float2 gg = *(const float2*)&lnG[col];
                float2 bb = *(const float2*)&lnB[col];
                float o00 = fmaxf((acc[mt][nt][0]-mu0)*r0v*gg.x + bb.x, 0.f);
                float o01 = fmaxf((acc[mt][nt][1]-mu0)*r0v*gg.y + bb.y, 0.f);
                float o10 = fmaxf((acc[mt][nt][2]-mu1)*r1v*gg.x + bb.x, 0.f);
                float o11 = fmaxf((acc[mt][nt][3]-mu1)*r1v*gg.y + bb.y, 0.f);
                if (RND) { o00=tfr(o00); o01=tfr(o01); o10=tfr(o10); o11=tfr(o11); }
                *(float2*)&C[(size_t)row*N + col]     = make_float2(o00, o01);
                *(float2*)&C[(size_t)(row+8)*N + col] = make_float2(o10, o11);
            }
        }
    } else {
        #pragma unroll
        for (int mt = 0; mt < MT; mt++) {
            #pragma unroll
            for (int nt = 0; nt < NT; nt++) {
                int row = m0 + wy*(16*MT) + mt*16 + g;
                int col = n0 + wx*(8*NT) + nt*8 + t*2;
                float2 bi = *(const float2*)&bias[col];
                float o00 = acc[mt][nt][0]+bi.x, o01 = acc[mt][nt][1]+bi.y;
                float o10 = acc[mt][nt][2]+bi.x, o11 = acc[mt][nt][3]+bi.y;
                if (resid) {
                    float2 r0 = *(const float2*)&resid[(size_t)row*N + col];
                    float2 r1 = *(const float2*)&resid[(size_t)(row+8)*N + col];
                    o00 += r0.x; o01 += r0.y; o10 += r1.x; o11 += r1.y;
                }
                if (RND) { o00=tfr(o00); o01=tfr(o01); o10=tfr(o10); o11=tfr(o11); }
                *(float2*)&C[(size_t)row*N + col]     = make_float2(o00, o01);
                *(float2*)&C[(size_t)(row+8)*N + col] = make_float2(o10, o11);
            }
        }
    }
}
#define GEMM_SMEM(MT,BN) (((BN)==256?2:3)*(((MT)*32+(BN))*36)*4)

// ---- dim_reduce GEMM + BN/ReLU/mean epilogue ----
#define DSTG (32*132 + 128*36)
#define DIMR_SMEM_BYTES (3*DSTG*4)
__global__ __launch_bounds__(256,2) void k_dimreduce_t(
    const float* __restrict__ feats, const float* __restrict__ W,
    const float* __restrict__ cb, const float* __restrict__ gamma,
    const float* __restrict__ beta, const float* __restrict__ mean,
    const float* __restrict__ var)
{
    extern __shared__ float fs[];
    unsigned sbase = smem_u32(fs);
    int m0 = blockIdx.y*128, n0 = blockIdx.x*128;
    int nb = m0 >> 4;
    int tid = threadIdx.x;
    int warp = tid >> 5, lane = tid & 31;
    int wy = warp >> 2, wx = warp & 3;
    int g = lane >> 2, t = lane & 3;
    float acc[4][4][4] = {};
    int lhw = (tid & 3)*4, lc = (tid >> 2) & 31, lnd = tid >> 7;
    int lr = tid >> 3, lkv = (tid & 7)*4;

    auto issue = [&](int k0, int st) {
        #pragma unroll
        for (int j = 0; j < 4; j++) {
            int nd = lnd + j*2;
            cpa16(sbase + (st*DSTG + lc*132 + nd*16 + lhw)*4,
                  &feats[(size_t)(nb+nd)*4096 + (k0+lc)*16 + lhw]);
            int r = lr + j*32;
            cpa16(sbase + (st*DSTG + 4224 + r*36 + lkv)*4, &W[(size_t)(n0+r)*256 + k0 + lkv]);
        }
        cpa_commit();
    };

    issue(0, 0); issue(32, 1);
    for (int i = 0; i < 8; i++) {
        if (i < 7) cpa_wait1(); else cpa_wait0();
        __syncthreads();
        if (i < 6) issue((i+2)*32, (i+2)%3);
        const float* sAT = fs + (i%3)*DSTG;
        const float* sB  = sAT + 4224;
        #pragma unroll
        for (int kc = 0; kc < 4; kc++) {
            unsigned a[4][4], b[4][2];
            #pragma unroll
            for (int mt = 0; mt < 4; mt++) {
                int r = wy*64 + mt*16 + g;
                a[mt][0] = f2tf(sAT[(kc*8 + t)*132 + r]);
                a[mt][1] = f2tf(sAT[(kc*8 + t)*132 + r + 8]);
                a[mt][2] = f2tf(sAT[(kc*8 + t + 4)*132 + r]);
                a[mt][3] = f2tf(sAT[(kc*8 + t + 4)*132 + r + 8]);
            }
            #pragma unroll
            for (int nt = 0; nt < 4; nt++) {
                int r = wx*32 + nt*8 + g;
                b[nt][0] = F2U(sB[r*36 + kc*8 + t]);
                b[nt][1] = F2U(sB[r*36 + kc*8 + t + 4]);
            }
            #pragma unroll
            for (int mt = 0; mt < 4; mt++)
                #pragma unroll
                for (int nt = 0; nt < 4; nt++)
                    mma8(acc[mt][nt], a[mt], b[nt]);
        }
        __syncthreads();
    }
    #pragma unroll
    for (int mt = 0; mt < 4; mt++) {
        int node = nb + wy*4 + mt;
        #pragma unroll
        for (int nt = 0; nt < 4; nt++) {
            int col = n0 + wx*32 + nt*8 + t*2;
            float s0 = gamma[col]   * rsqrtf(var[col]   + 1e-5f);
            float s1 = gamma[col+1] * rsqrtf(var[col+1] + 1e-5f);
            float c0 = (cb[col]   - mean[col])  *s0 + beta[col];
            float c1 = (cb[col+1] - mean[col+1])*s1 + beta[col+1];
            float sum0 = fmaxf(acc[mt][nt][0]*s0 + c0, 0.f) + fmaxf(acc[mt][nt][2]*s0 + c0, 0.f);
            float sum1 = fmaxf(acc[mt][nt][1]*s1 + c1, 0.f) + fmaxf(acc[mt][nt][3]*s1 + c1, 0.f);
            #pragma unroll
            for (int msk = 4; msk < 32; msk <<= 1) {
                sum0 += __shfl_xor_sync(0xffffffffu, sum0, msk);
                sum1 += __shfl_xor_sync(0xffffffffu, sum1, msk);
            }
            if (g == 0) {
                d_x[node*HIDD + col]   = tfr(sum0 * (1.f/16.f));
                d_x[node*HIDD + col+1] = tfr(sum1 * (1.f/16.f));
            }
        }
    }
}

// ---- flash attention: q-tile 128, KV-tile 128 (two 64-key halves), 2-stage -
#define AQ   0
#define AKV  4608
#define ASTG 9216
#define ATT_SMEM_BYTES ((AKV + 2*ASTG)*4)

__global__ __launch_bounds__(256,2) void k_attn_t(const float* __restrict__ qkv,
                                                  float* __restrict__ out)
{
    extern __shared__ float fs[];
    unsigned sbase = smem_u32(fs);
    int h  = blockIdx.y;
    int q0 = blockIdx.x * 128;
    int tid = threadIdx.x;
    int warp = tid >> 5, lane = tid & 31;
    int g = lane >> 2, t = lane & 3;
    const float scale = 0.17677669529663689f;   // 32^-0.5
    int lr = tid >> 3, lkv = (tid & 7)*4;
    int qr = warp*16 + g;

    // Q tile (scaled, tf32 bits)
    #pragma unroll
    for (int j = 0; j < 4; j++) {
        int r = lr + j*32;
        float4 v = *(const float4*)&qkv[(size_t)(q0+r)*768 + h*32 + lkv];
        float* p = &fs[AQ + r*36 + lkv];
        p[0]=tfr(v.x*scale); p[1]=tfr(v.y*scale);
        p[2]=tfr(v.z*scale); p[3]=tfr(v.w*scale);
    }

    auto issue = [&](int kt) {
        unsigned kb = sbase + (AKV + (kt&1)*ASTG)*4;
        #pragma unroll
        for (int j = 0; j < 4; j++) {
            int r = lr + j*32;
            int pr = (r & ~7) | (((r & 3) << 1) | ((r >> 2) & 1));  // K row permute
            const float* srcK = &qkv[(size_t)(kt*128+r)*768 + 256 + h*32 + lkv];
            cpa16(kb + (pr*36 + lkv)*4,          srcK);
            cpa16(kb + ((4608 + r*36) + lkv)*4,  srcK + 256);
        }
        cpa_commit();
    };

    issue(0);
    __syncthreads();   // Q visible to all

    // Q fragments -> registers (loop-invariant)
    unsigned qa[4][4];
    #pragma unroll
    for (int kc = 0; kc < 4; kc++) {
        qa[kc][0] = F2U(fs[AQ + qr*36 + kc*8 + t]);
        qa[kc][1] = F2U(fs[AQ + (qr+8)*36 + kc*8 + t]);
        qa[kc][2] = F2U(fs[AQ + qr*36 + kc*8 + t + 4]);
        qa[kc][3] = F2U(fs[AQ + (qr+8)*36 + kc*8 + t + 4]);
    }

    float l0 = 0.f, l1 = 0.f;
    float o[4][4] = {};

    for (int it = 0; it < 32; it++) {
        cpa_wait0();
        __syncthreads();
        if (it < 31) issue(it+1);
        const float* sKt = fs + AKV + (it&1)*ASTG;

        #pragma unroll
        for (int half = 0; half < 2; half++) {
            const float* sK = sKt + half*64*36;
            const float* sV = sKt + 4608 + half*64*36;

            // S = Q @ K^T (columns in permuted key order)
            float s[8][4] = {};
            #pragma unroll
            for (int kc = 0; kc < 4; kc++) {
                unsigned b[8][2];
                #pragma unroll
                for (int nt = 0; nt < 8; nt++) {
                    b[nt][0] = F2U(sK[(nt*8+g)*36 + kc*8 + t]);
                    b[nt][1] = F2U(sK[(nt*8+g)*36 + kc*8 + t + 4]);
                }
                #pragma unroll
                for (int nt = 0; nt < 8; nt++) mma8(s[nt], qa[kc], b[nt]);
            }

            // exp, accumulate l, round to tf32 in place
            #pragma unroll
            for (int nt = 0; nt < 8; nt++) {
                float e0 = __expf(s[nt][0]); l0 += e0; s[nt][0] = __uint_as_float(f2tf(e0));
                float e1 = __expf(s[nt][1]); l0 += e1; s[nt][1] = __uint_as_float(f2tf(e1));
                float e2 = __expf(s[nt][2]); l1 += e2; s[nt][2] = __uint_as_float(f2tf(e2));
                float e3 = __expf(s[nt][3]); l1 += e3; s[nt][3] = __uint_as_float(f2tf(e3));
            }

            // O += P @ V : S frags ARE the PV A-frags (key permutation)
            #pragma unroll
            for (int kc = 0; kc < 8; kc++) {
                unsigned a[4] = { F2U(s[kc][0]), F2U(s[kc][2]), F2U(s[kc][1]), F2U(s[kc][3]) };
                unsigned b[4][2];
                #pragma unroll
                for (int dt = 0; dt < 4; dt++) {
                    b[dt][0] = F2U(sV[(kc*8 + t)*36 + dt*8 + g]);
                    b[dt][1] = F2U(sV[(kc*8 + t + 4)*36 + dt*8 + g]);
                }
                #pragma unroll
                for (int dt = 0; dt < 4; dt++) mma8(o[dt], a, b[dt]);
            }
        }
    }

    #pragma unroll
    for (int msk = 1; msk < 4; msk <<= 1) {
        l0 += __shfl_xor_sync(0xffffffffu, l0, msk);
        l1 += __shfl_xor_sync(0xffffffffu, l1, msk);
    }
    float inv0 = 1.f / l0, inv1 = 1.f / l1;
    int r = q0 + qr;
    #pragma unroll
    for (int dt = 0; dt < 4; dt++) {
        int col = h*32 + dt*8 + t*2;
        *(float2*)&out[(size_t)r*256 + col]     = make_float2(tfr(o[dt][0]*inv0), tfr(o[dt][1]*inv0));
        *(float2*)&out[(size_t)(r+8)*256 + col] = make_float2(tfr(o[dt][2]*inv1), tfr(o[dt][3]*inv1));
    }
}

// ---- graph ----
__global__ void k_deg(const void* __restrict__ edges, const float* __restrict__ ew) {
    int e = blockIdx.x*blockDim.x + threadIdx.x;
    if (e >= NEDGE) return;
    int r, c; get_edge(edges, e, r, c);
    float w = ew[e];
    atomicAdd(&d_deg[r], w);  atomicAdd(&d_deg[c], w);
    atomicAdd(&d_rowcnt[r], 1); atomicAdd(&d_rowcnt[c], 1);
}
__global__ __launch_bounds__(1024) void k_scan() {
    __shared__ int s[1024];
    int tid = threadIdx.x;
    #pragma unroll
    for (int j = 0; j < 4; j++) {
        int i = tid*4 + j;
        d_dinv[i] = rsqrtf(d_deg[i] + 1e-6f);
    }
    int c0 = d_rowcnt[tid*4], c1 = d_rowcnt[tid*4+1], c2 = d_rowcnt[tid*4+2], c3 = d_rowcnt[tid*4+3];
    int p0 = c0, p1 = p0+c1, p2 = p1+c2, p3 = p2+c3;
    s[tid] = p3;
    __syncthreads();
    for (int off = 1; off < 1024; off <<= 1) {
        int v = (tid >= off) ? s[tid-off] : 0;
        __syncthreads(); s[tid] += v; __syncthreads();
    }
    int excl = s[tid] - p3;
    d_rowptr[tid*4] = excl; d_rowptr[tid*4+1] = excl+p0;
    d_rowptr[tid*4+2] = excl+p1; d_rowptr[tid*4+3] = excl+p2;
    if (tid == 1023) d_rowptr[NNODES] = s[1023];
}
__global__ void k_fill(const void* __restrict__ edges, const float* __restrict__ ew) {
    int e = blockIdx.x*blockDim.x + threadIdx.x;
    if (e >= NEDGE) return;
    int r, c; get_edge(edges, e, r, c);
    float w = ew[e];
    int p1 = d_rowptr[r] + atomicAdd(&d_fillcnt[r], 1);
    d_col[p1] = c;  d_coef[p1] = w * d_dinv[c];
    int p2 = d_rowptr[c] + atomicAdd(&d_fillcnt[c], 1);
    d_col[p2] = r;  d_coef[p2] = w * d_dinv[r];
}
// 4-way unrolled gather SpMM (MLP=4 hides L2 latency)
__global__ __launch_bounds__(256) void k_spmm(const float* __restrict__ xin,
                                              float* __restrict__ xout) {
    int n = blockIdx.x, t = threadIdx.x;
    int s = d_rowptr[n], e = d_rowptr[n+1];
    float a0 = 0.f, a1 = 0.f, a2 = 0.f, a3 = 0.f;
    int j = s;
    for (; j + 4 <= e; j += 4) {
        int   c0 = __ldg(&d_col[j]),   c1 = __ldg(&d_col[j+1]);
        int   c2 = __ldg(&d_col[j+2]), c3 = __ldg(&d_col[j+3]);
        float f0 = __ldg(&d_coef[j]),  f1 = __ldg(&d_coef[j+1]);
        float f2 = __ldg(&d_coef[j+2]),f3 = __ldg(&d_coef[j+3]);
        a0 += f0 * xin[(size_t)c0*HIDD + t];
        a1 += f1 * xin[(size_t)c1*HIDD + t];
        a2 += f2 * xin[(size_t)c2*HIDD + t];
        a3 += f3 * xin[(size_t)c3*HIDD + t];
    }
    for (; j < e; j++)
        a0 += __ldg(&d_coef[j]) * xin[(size_t)__ldg(&d_col[j])*HIDD + t];
    xout[(size_t)n*HIDD + t] = tfr(d_dinv[n] * ((a0+a1)+(a2+a3)));
}

extern "C" void kernel_launch(void* const* d_in, const int* in_sizes, int n_in,
                              void* d_out, int out_size) {
    const float* node_feats = (const float*)d_in[0];
    const void*  edges      = d_in[1];
    const float* ew         = (const float*)d_in[2];
    const float* conv_b  = (const float*)d_in[4];
    const float* bn_g    = (const float*)d_in[5];
    const float* bn_b    = (const float*)d_in[6];
    const float* bn_m    = (const float*)d_in[7];
    const float* bn_v    = (const float*)d_in[8];
    const float* qkv_b   = (const float*)d_in[10];
    const float* proj_b  = (const float*)d_in[12];
    const float* gcn1_b  = (const float*)d_in[14];
    const float* ln1_g   = (const float*)d_in[15];
    const float* ln1_b   = (const float*)d_in[16];
    const float* gcn2_b  = (const float*)d_in[18];
    const float* ln2_g   = (const float*)d_in[19];
    const float* ln2_b   = (const float*)d_in[20];
    const float* sc_b    = (const float*)d_in[22];
    float* out = (float*)d_out;

    float *p_x,*p_qkv,*p_att,*p_x2,*p_s1,*p_g1,*p_s2,*p_g2;
    float *p_wq,*p_wp,*p_w1,*p_w2,*p_ws,*p_wc;
    cudaGetSymbolAddress((void**)&p_x, d_x);   cudaGetSymbolAddress((void**)&p_qkv, d_qkv);
    cudaGetSymbolAddress((void**)&p_att, d_att); cudaGetSymbolAddress((void**)&p_x2, d_x2);
    cudaGetSymbolAddress((void**)&p_s1, d_s1); cudaGetSymbolAddress((void**)&p_g1, d_g1);
    cudaGetSymbolAddress((void**)&p_s2, d_s2); cudaGetSymbolAddress((void**)&p_g2, d_g2);
    cudaGetSymbolAddress((void**)&p_wq, d_wq); cudaGetSymbolAddress((void**)&p_wp, d_wp);
    cudaGetSymbolAddress((void**)&p_w1, d_w1); cudaGetSymbolAddress((void**)&p_w2, d_w2);
    cudaGetSymbolAddress((void**)&p_ws, d_ws); cudaGetSymbolAddress((void**)&p_wc, d_wc);

    static int done = 0;
    if (!done) {
        cudaFuncSetAttribute((const void*)k_gemm_t<4,128,true,false>,  cudaFuncAttributeMaxDynamicSharedMemorySize, GEMM_SMEM(4,128));
        cudaFuncSetAttribute((const void*)k_gemm_t<2,128,false,false>, cudaFuncAttributeMaxDynamicSharedMemorySize, GEMM_SMEM(2,128));
        cudaFuncSetAttribute((const void*)k_gemm_t<1,256,true,true>,   cudaFuncAttributeMaxDynamicSharedMemorySize, GEMM_SMEM(1,256));
        cudaFuncSetAttribute((const void*)k_gemm_t<1,128,false,true>,  cudaFuncAttributeMaxDynamicSharedMemorySize, GEMM_SMEM(1,128));
        cudaFuncSetAttribute((const void*)k_gemm_t<1,128,false,false>, cudaFuncAttributeMaxDynamicSharedMemorySize, GEMM_SMEM(1,128));
        cudaFuncSetAttribute(k_dimreduce_t, cudaFuncAttributeMaxDynamicSharedMemorySize, DIMR_SMEM_BYTES);
        cudaFuncSetAttribute(k_attn_t,      cudaFuncAttributeMaxDynamicSharedMemorySize, ATT_SMEM_BYTES);
        done = 1;
    }

    k_init<<<16, 256>>>((const int*)edges);
    k_round_all<<<(RW_TOT+255)/256, 256>>>((const float*)d_in[9], (const float*)d_in[11],
        (const float*)d_in[13], (const float*)d_in[17], (const float*)d_in[21], (const float*)d_in[3]);

    k_deg<<<NEDGE/256, 256>>>(edges, ew);
    k_scan<<<1, 1024>>>();
    k_fill<<<NEDGE/256, 256>>>(edges, ew);

    k_dimreduce_t<<<dim3(2, 512), 256, DIMR_SMEM_BYTES>>>(node_feats, p_wc, conv_b, bn_g, bn_b, bn_m, bn_v);

    // qkv = x @ Wq^T + b  (rounded for attention)
    k_gemm_t<4,128,true,false><<<dim3(6, 32), 256, GEMM_SMEM(4,128)>>>(
        p_x, p_wq, qkv_b, nullptr, nullptr, nullptr, p_qkv, 768);

    k_attn_t<<<dim3(32, NHEADS), 256, ATT_SMEM_BYTES>>>(p_qkv, p_att);

    // x2 = att @ Wp^T + b
    k_gemm_t<2,128,false,false><<<dim3(2, 64), 256, GEMM_SMEM(2,128)>>>(
        p_att, p_wp, proj_b, nullptr, nullptr, nullptr, p_x2, 256);

    // gcn1: SpMM -> GEMM+LN+ReLU (fused, full-row BN=256)
    k_spmm<<<NNODES, 256>>>(p_x2, p_s1);
    k_gemm_t<1,256,true,true><<<dim3(1, 128), 256, GEMM_SMEM(1,256)>>>(
        p_s1, p_w1, gcn1_b, nullptr, ln1_g, ln1_b, p_g1, 256);

    // gcn2: SpMM -> GEMM+LN+ReLU (fused, full-row BN=128)
    k_spmm<<<NNODES, 256>>>(p_g1, p_s2);
    k_gemm_t<1,128,false,true><<<dim3(1, 128), 256, GEMM_SMEM(1,128)>>>(
        p_s2, p_w2, gcn2_b, nullptr, ln2_g, ln2_b, p_g2, 128);

    // out = g1 @ Ws^T + b + g2
    k_gemm_t<1,128,false,false><<<dim3(1, 128), 256, GEMM_SMEM(1,128)>>>(
        p_g1, p_ws, sc_b, p_g2, nullptr, nullptr, out, 128);
}

// round 14
// speedup vs baseline: 1.0124x; 1.0124x over previous
#include <cuda_runtime.h>
#include <cstdint>
#include <math.h>

#define NNODES 4096
#define HIDD   256
#define NHEADS 8
#define NEDGE  65536
#define NDIR   (2*NEDGE)

__device__ float d_x   [NNODES*HIDD];
__device__ float d_qkv [NNODES*3*HIDD];
__device__ float d_att [NNODES*HIDD];
__device__ float d_x2  [NNODES*HIDD];
__device__ float d_s1  [NNODES*HIDD];
__device__ float d_g1  [NNODES*HIDD];
__device__ float d_s2  [NNODES*HIDD];
__device__ float d_deg [NNODES];
__device__ float d_dinv[NNODES];
__device__ int   d_rowcnt[NNODES];
__device__ int   d_fillcnt[NNODES];
__device__ int   d_rowptr[NNODES+1];
__device__ int   d_col [NDIR];
__device__ float d_coef[NDIR];
__device__ int   d_e64flag;
__device__ float d_wq[768*256];
__device__ float d_wp[256*256];
__device__ float d_w1[256*256];
__device__ float d_w2[128*256];
__device__ float d_ws[128*256];
__device__ float d_wc[256*256];

__device__ __forceinline__ unsigned f2tf(float x) {
    unsigned r; asm("cvt.rna.tf32.f32 %0, %1;" : "=r"(r) : "f"(x)); return r;
}
__device__ __forceinline__ float tfr(float x) { return __uint_as_float(f2tf(x)); }
__device__ __forceinline__ unsigned F2U(float x) { return __float_as_uint(x); }
__device__ __forceinline__ void mma8(float* d, const unsigned* a, const unsigned* b) {
    asm volatile("mma.sync.aligned.m16n8k8.row.col.f32.tf32.tf32.f32 "
        "{%0,%1,%2,%3}, {%4,%5,%6,%7}, {%8,%9}, {%0,%1,%2,%3};"
        : "+f"(d[0]), "+f"(d[1]), "+f"(d[2]), "+f"(d[3])
        : "r"(a[0]), "r"(a[1]), "r"(a[2]), "r"(a[3]), "r"(b[0]), "r"(b[1]));
}
__device__ __forceinline__ void cpa16(unsigned dst, const float* src) {
    asm volatile("cp.async.cg.shared.global [%0], [%1], 16;" :: "r"(dst), "l"(src));
}
__device__ __forceinline__ void cpa_commit() { asm volatile("cp.async.commit_group;"); }
__device__ __forceinline__ void cpa_wait1()  { asm volatile("cp.async.wait_group 1;"); }
__device__ __forceinline__ void cpa_wait0()  { asm volatile("cp.async.wait_group 0;"); }
__device__ __forceinline__ unsigned smem_u32(const void* p) {
    return (unsigned)__cvta_generic_to_shared(p);
}

// ---- misc ----
__global__ void k_init(const int* __restrict__ e) {
    int i = blockIdx.x*256 + threadIdx.x;
    if (i < NNODES) { d_deg[i]=0.f; d_rowcnt[i]=0; d_fillcnt[i]=0; }
    if (blockIdx.x == 0 && threadIdx.x == 0) {
        int z = 0;
        #pragma unroll
        for (int j = 1; j < 16; j += 2) z |= e[j];
        d_e64flag = (z == 0) ? 1 : 0;
    }
}
#define RW_TOT 458752
__global__ void k_round_all(const float* __restrict__ qw, const float* __restrict__ pw,
                            const float* __restrict__ w1, const float* __restrict__ w2,
                            const float* __restrict__ sw, const float* __restrict__ cw) {
    int j = blockIdx.x*256 + threadIdx.x;
    if (j >= RW_TOT) return;
    if (j < 196608) { d_wq[j] = tfr(qw[j]); return; }  j -= 196608;
    if (j < 65536)  { d_wp[j] = tfr(pw[j]); return; }  j -= 65536;
    if (j < 65536)  { d_w1[j] = tfr(w1[j]); return; }  j -= 65536;
    if (j < 32768)  { d_w2[j] = tfr(w2[j]); return; }  j -= 32768;
    if (j < 32768)  { d_ws[j] = tfr(sw[j]); return; }  j -= 32768;
    d_wc[j] = tfr(cw[j]);
}
__device__ __forceinline__ void get_edge(const void* edges, int e, int& r, int& c) {
    if (d_e64flag) { const long long* p = (const long long*)edges; r = (int)p[2*e]; c = (int)p[2*e+1]; }
    else           { const int* p = (const int*)edges;             r = p[2*e];      c = p[2*e+1]; }
}

// ---- tf32 GEMM: C[M,N] = A[M,256] @ B[N,256]^T + bias (+resid) (+LN+ReLU) --
// block tile (MT*32) x BN, 8 warps (2 x 4), warp tile (MT*16) x (BN/4).
// LN=true requires BN == N (full row in one block); resid added AFTER LN+ReLU.
template<int MT, int BN, bool RND, bool LN>
__global__ __launch_bounds__(256,2) void k_gemm_t(
    const float* __restrict__ A, const float* __restrict__ B,
    const float* __restrict__ bias, const float* __restrict__ resid,
    const float* __restrict__ lnG, const float* __restrict__ lnB,
    float* __restrict__ C, int N)
{
    extern __shared__ float fs[];
    const int BM  = MT*32;
    const int NT  = BN/32;
    const int ASZ = BM*36;
    const int STG = ASZ + BN*36;
    const int NST = (BN == 256) ? 2 : 3;
    unsigned sbase = smem_u32(fs);
    const int K = 256;
    int m0 = blockIdx.y*BM, n0 = blockIdx.x*BN;
    int tid = threadIdx.x;
    int warp = tid >> 5, lane = tid & 31;
    int wy = warp >> 2, wx = warp & 3;
    int g = lane >> 2, t = lane & 3;
    float acc[MT][NT][4] = {};
    int lr = tid >> 3, lkv = (tid & 7)*4;

    auto issue = [&](int k0, int st) {
        #pragma unroll
        for (int j = 0; j < MT; j++) {
            int r = lr + j*32;
            cpa16(sbase + (st*STG + r*36 + lkv)*4, &A[(size_t)(m0+r)*K + k0 + lkv]);
        }
        #pragma unroll
        for (int j = 0; j < BN/32; j++) {
            int r = lr + j*32;
            cpa16(sbase + (st*STG + ASZ + r*36 + lkv)*4, &B[(size_t)(n0+r)*K + k0 + lkv]);
        }
        cpa_commit();
    };

    issue(0, 0);
    if (NST == 3) issue(32, 1);
    for (int i = 0; i < 8; i++) {
        if (NST == 3) { if (i < 7) cpa_wait1(); else cpa_wait0(); }
        else cpa_wait0();
        __syncthreads();
        if (i < 8 - (NST-1)) issue((i+NST-1)*32, (i+NST-1)%NST);
        const float* sA = fs + (i%NST)*STG;
        const float* sB = sA + ASZ;
        #pragma unroll
        for (int kc = 0; kc < 4; kc++) {
            unsigned a[MT][4], b[NT][2];
            #pragma unroll
            for (int mt = 0; mt < MT; mt++) {
                int r = wy*(16*MT) + mt*16 + g;
                a[mt][0] = F2U(sA[r*36 + kc*8 + t]);
                a[mt][1] = F2U(sA[(r+8)*36 + kc*8 + t]);
                a[mt][2] = F2U(sA[r*36 + kc*8 + t + 4]);
                a[mt][3] = F2U(sA[(r+8)*36 + kc*8 + t + 4]);
            }
            #pragma unroll
            for (int nt = 0; nt < NT; nt++) {
                int r = wx*(8*NT) + nt*8 + g;
                b[nt][0] = F2U(sB[r*36 + kc*8 + t]);
                b[nt][1] = F2U(sB[r*36 + kc*8 + t + 4]);
            }
            #pragma unroll
            for (int mt = 0; mt < MT; mt++)
                #pragma unroll
                for (int nt = 0; nt < NT; nt++)
                    mma8(acc[mt][nt], a[mt], b[nt]);
        }
        __syncthreads();
    }

    if (LN) {
        float* redS = fs;
        float* redQ = fs + BM*4;
        #pragma unroll
        for (int mt = 0; mt < MT; mt++) {
            float sl = 0.f, ql = 0.f, sh = 0.f, qh = 0.f;
            #pragma unroll
            for (int nt = 0; nt < NT; nt++) {
                int col = n0 + wx*(8*NT) + nt*8 + t*2;
                float2 bi = *(const float2*)&bias[col];
                float v0 = acc[mt][nt][0]+bi.x, v1 = acc[mt][nt][1]+bi.y;
                float w0 = acc[mt][nt][2]+bi.x, w1 = acc[mt][nt][3]+bi.y;
                acc[mt][nt][0]=v0; acc[mt][nt][1]=v1; acc[mt][nt][2]=w0; acc[mt][nt][3]=w1;
                sl += v0+v1; ql += v0*v0+v1*v1;
                sh += w0+w1; qh += w0*w0+w1*w1;
            }
            #pragma unroll
            for (int msk = 1; msk < 4; msk <<= 1) {
                sl += __shfl_xor_sync(0xffffffffu, sl, msk);
                ql += __shfl_xor_sync(0xffffffffu, ql, msk);
                sh += __shfl_xor_sync(0xffffffffu, sh, msk);
                qh += __shfl_xor_sync(0xffffffffu, qh, msk);
            }
            if (t == 0) {
                int rl = wy*(16*MT) + mt*16 + g;
                redS[rl*4 + wx] = sl;     redQ[rl*4 + wx] = ql;
                redS[(rl+8)*4 + wx] = sh; redQ[(rl+8)*4 + wx] = qh;
            }
        }
        __syncthreads();
        #pragma unroll
        for (int mt = 0; mt < MT; mt++) {
            int rl = wy*(16*MT) + mt*16 + g;
            float S0 = redS[rl*4]+redS[rl*4+1]+redS[rl*4+2]+redS[rl*4+3];
            float Q0 = redQ[rl*4]+redQ[rl*4+1]+redQ[rl*4+2]+redQ[rl*4+3];
            float S1 = redS[(rl+8)*4]+redS[(rl+8)*4+1]+redS[(rl+8)*4+2]+redS[(rl+8)*4+3];
            float Q1 = redQ[(rl+8)*4]+redQ[(rl+8)*4+1]+redQ[(rl+8)*4+2]+redQ[(rl+8)*4+3];
            float mu0 = S0/BN, r0v = rsqrtf(Q0/BN - mu0*mu0 + 1e-5f);
            float mu1 = S1/BN, r1v = rsqrtf(Q1/BN - mu1*mu1 + 1e-5f);
            int row = m0 + rl;
            #pragma unroll
            for (int nt = 0; nt < NT; nt++) {
                int col = n0 + wx*(8*NT) + nt*8 + t*2;
                float2 gg = *(const float2*)&lnG[col];
                float2 bb = *(const float2*)&lnB[col];
                float o00 = fmaxf((acc[mt][nt][0]-mu0)*r0v*gg.x + bb.x, 0.f);
                float o01 = fmaxf((acc[mt][nt][1]-mu0)*r0v*gg.y + bb.y, 0.f);
                float o10 = fmaxf((acc[mt][nt][2]-mu1)*r1v*gg.x + bb.x, 0.f);
                float o11 = fmaxf((acc[mt][nt][3]-mu1)*r1v*gg.y + bb.y, 0.f);
                if (resid) {
                    float2 r0 = *(const float2*)&resid[(size_t)row*N + col];
                    float2 r1 = *(const float2*)&resid[(size_t)(row+8)*N + col];
                    o00 += r0.x; o01 += r0.y; o10 += r1.x; o11 += r1.y;
                }
                if (RND) { o00=tfr(o00); o01=tfr(o01); o10=tfr(o10); o11=tfr(o11); }
                *(float2*)&C[(size_t)row*N + col]     = make_float2(o00, o01);
                *(float2*)&C[(size_t)(row+8)*N + col] = make_float2(o10, o11);
            }
        }
    } else {
        #pragma unroll
        for (int mt = 0; mt < MT; mt++) {
            #pragma unroll
            for (int nt = 0; nt < NT; nt++) {
                int row = m0 + wy*(16*MT) + mt*16 + g;
                int col = n0 + wx*(8*NT) + nt*8 + t*2;
                float2 bi = *(const float2*)&bias[col];
                float o00 = acc[mt][nt][0]+bi.x, o01 = acc[mt][nt][1]+bi.y;
                float o10 = acc[mt][nt][2]+bi.x, o11 = acc[mt][nt][3]+bi.y;
                if (resid) {
                    float2 r0 = *(const float2*)&resid[(size_t)row*N + col];
                    float2 r1 = *(const float2*)&resid[(size_t)(row+8)*N + col];
                    o00 += r0.x; o01 += r0.y; o10 += r1.x; o11 += r1.y;
                }
                if (RND) { o00=tfr(o00); o01=tfr(o01); o10=tfr(o10); o11=tfr(o11); }
                *(float2*)&C[(size_t)row*N + col]     = make_float2(o00, o01);
                *(float2*)&C[(size_t)(row+8)*N + col] = make_float2(o10, o11);
            }
        }
    }
}
#define GEMM_SMEM(MT,BN) (((BN)==256?2:3)*(((MT)*32+(BN))*36)*4)

// ---- dim_reduce GEMM + BN/ReLU/mean epilogue ----
#define DSTG (32*132 + 128*36)
#define DIMR_SMEM_BYTES (3*DSTG*4)
__global__ __launch_bounds__(256,2) void k_dimreduce_t(
    const float* __restrict__ feats, const float* __restrict__ W,
    const float* __restrict__ cb, const float* __restrict__ gamma,
    const float* __restrict__ beta, const float* __restrict__ mean,
    const float* __restrict__ var)
{
    extern __shared__ float fs[];
    unsigned sbase = smem_u32(fs);
    int m0 = blockIdx.y*128, n0 = blockIdx.x*128;
    int nb = m0 >> 4;
    int tid = threadIdx.x;
    int warp = tid >> 5, lane = tid & 31;
    int wy = warp >> 2, wx = warp & 3;
    int g = lane >> 2, t = lane & 3;
    float acc[4][4][4] = {};
    int lhw = (tid & 3)*4, lc = (tid >> 2) & 31, lnd = tid >> 7;
    int lr = tid >> 3, lkv = (tid & 7)*4;

    auto issue = [&](int k0, int st) {
        #pragma unroll
        for (int j = 0; j < 4; j++) {
            int nd = lnd + j*2;
            cpa16(sbase + (st*DSTG + lc*132 + nd*16 + lhw)*4,
                  &feats[(size_t)(nb+nd)*4096 + (k0+lc)*16 + lhw]);
            int r = lr + j*32;
            cpa16(sbase + (st*DSTG + 4224 + r*36 + lkv)*4, &W[(size_t)(n0+r)*256 + k0 + lkv]);
        }
        cpa_commit();
    };

    issue(0, 0); issue(32, 1);
    for (int i = 0; i < 8; i++) {
        if (i < 7) cpa_wait1(); else cpa_wait0();
        __syncthreads();
        if (i < 6) issue((i+2)*32, (i+2)%3);
        const float* sAT = fs + (i%3)*DSTG;
        const float* sB  = sAT + 4224;
        #pragma unroll
        for (int kc = 0; kc < 4; kc++) {
            unsigned a[4][4], b[4][2];
            #pragma unroll
            for (int mt = 0; mt < 4; mt++) {
                int r = wy*64 + mt*16 + g;
                a[mt][0] = f2tf(sAT[(kc*8 + t)*132 + r]);
                a[mt][1] = f2tf(sAT[(kc*8 + t)*132 + r + 8]);
                a[mt][2] = f2tf(sAT[(kc*8 + t + 4)*132 + r]);
                a[mt][3] = f2tf(sAT[(kc*8 + t + 4)*132 + r + 8]);
            }
            #pragma unroll
            for (int nt = 0; nt < 4; nt++) {
                int r = wx*32 + nt*8 + g;
                b[nt][0] = F2U(sB[r*36 + kc*8 + t]);
                b[nt][1] = F2U(sB[r*36 + kc*8 + t + 4]);
            }
            #pragma unroll
            for (int mt = 0; mt < 4; mt++)
                #pragma unroll
                for (int nt = 0; nt < 4; nt++)
                    mma8(acc[mt][nt], a[mt], b[nt]);
        }
        __syncthreads();
    }
    #pragma unroll
    for (int mt = 0; mt < 4; mt++) {
        int node = nb + wy*4 + mt;
        #pragma unroll
        for (int nt = 0; nt < 4; nt++) {
            int col = n0 + wx*32 + nt*8 + t*2;
            float s0 = gamma[col]   * rsqrtf(var[col]   + 1e-5f);
            float s1 = gamma[col+1] * rsqrtf(var[col+1] + 1e-5f);
            float c0 = (cb[col]   - mean[col])  *s0 + beta[col];
            float c1 = (cb[col+1] - mean[col+1])*s1 + beta[col+1];
            float sum0 = fmaxf(acc[mt][nt][0]*s0 + c0, 0.f) + fmaxf(acc[mt][nt][2]*s0 + c0, 0.f);
            float sum1 = fmaxf(acc[mt][nt][1]*s1 + c1, 0.f) + fmaxf(acc[mt][nt][3]*s1 + c1, 0.f);
            #pragma unroll
            for (int msk = 4; msk < 32; msk <<= 1) {
                sum0 += __shfl_xor_sync(0xffffffffu, sum0, msk);
                sum1 += __shfl_xor_sync(0xffffffffu, sum1, msk);
            }
            if (g == 0) {
                d_x[node*HIDD + col]   = tfr(sum0 * (1.f/16.f));
                d_x[node*HIDD + col+1] = tfr(sum1 * (1.f/16.f));
            }
        }
    }
}

// ---- flash attention: q-tile 128, KV-tile 128 (two 64-key halves), 2-stage -
#define AQ   0
#define AKV  4608
#define ASTG 9216
#define ATT_SMEM_BYTES ((AKV + 2*ASTG)*4)

__global__ __launch_bounds__(256,2) void k_attn_t(const float* __restrict__ qkv,
                                                  float* __restrict__ out)
{
    extern __shared__ float fs[];
    unsigned sbase = smem_u32(fs);
    int h  = blockIdx.y;
    int q0 = blockIdx.x * 128;
    int tid = threadIdx.x;
    int warp = tid >> 5, lane = tid & 31;
    int g = lane >> 2, t = lane & 3;
    const float scale = 0.17677669529663689f;   // 32^-0.5
    int lr = tid >> 3, lkv = (tid & 7)*4;
    int qr = warp*16 + g;

    #pragma unroll
    for (int j = 0; j < 4; j++) {
        int r = lr + j*32;
        float4 v = *(const float4*)&qkv[(size_t)(q0+r)*768 + h*32 + lkv];
        float* p = &fs[AQ + r*36 + lkv];
        p[0]=tfr(v.x*scale); p[1]=tfr(v.y*scale);
        p[2]=tfr(v.z*scale); p[3]=tfr(v.w*scale);
    }

    auto issue = [&](int kt) {
        unsigned kb = sbase + (AKV + (kt&1)*ASTG)*4;
        #pragma unroll
        for (int j = 0; j < 4; j++) {
            int r = lr + j*32;
            int pr = (r & ~7) | (((r & 3) << 1) | ((r >> 2) & 1));  // K row permute
            const float* srcK = &qkv[(size_t)(kt*128+r)*768 + 256 + h*32 + lkv];
            cpa16(kb + (pr*36 + lkv)*4,          srcK);
            cpa16(kb + ((4608 + r*36) + lkv)*4,  srcK + 256);
        }
        cpa_commit();
    };

    issue(0);
    __syncthreads();

    unsigned qa[4][4];
    #pragma unroll
    for (int kc = 0; kc < 4; kc++) {
        qa[kc][0] = F2U(fs[AQ + qr*36 + kc*8 + t]);
        qa[kc][1] = F2U(fs[AQ + (qr+8)*36 + kc*8 + t]);
        qa[kc][2] = F2U(fs[AQ + qr*36 + kc*8 + t + 4]);
        qa[kc][3] = F2U(fs[AQ + (qr+8)*36 + kc*8 + t + 4]);
    }

    float l0 = 0.f, l1 = 0.f;
    float o[4][4] = {};

    for (int it = 0; it < 32; it++) {
        cpa_wait0();
        __syncthreads();
        if (it < 31) issue(it+1);
        const float* sKt = fs + AKV + (it&1)*ASTG;

        #pragma unroll
        for (int half = 0; half < 2; half++) {
            const float* sK = sKt + half*64*36;
            const float* sV = sKt + 4608 + half*64*36;

            float s[8][4] = {};
            #pragma unroll
            for (int kc = 0; kc < 4; kc++) {
                unsigned b[8][2];
                #pragma unroll
                for (int nt = 0; nt < 8; nt++) {
                    b[nt][0] = F2U(sK[(nt*8+g)*36 + kc*8 + t]);
                    b[nt][1] = F2U(sK[(nt*8+g)*36 + kc*8 + t + 4]);
                }
                #pragma unroll
                for (int nt = 0; nt < 8; nt++) mma8(s[nt], qa[kc], b[nt]);
            }

            #pragma unroll
            for (int nt = 0; nt < 8; nt++) {
                float e0 = __expf(s[nt][0]); l0 += e0; s[nt][0] = __uint_as_float(f2tf(e0));
                float e1 = __expf(s[nt][1]); l0 += e1; s[nt][1] = __uint_as_float(f2tf(e1));
                float e2 = __expf(s[nt][2]); l1 += e2; s[nt][2] = __uint_as_float(f2tf(e2));
                float e3 = __expf(s[nt][3]); l1 += e3; s[nt][3] = __uint_as_float(f2tf(e3));
            }

            #pragma unroll
            for (int kc = 0; kc < 8; kc++) {
                unsigned a[4] = { F2U(s[kc][0]), F2U(s[kc][2]), F2U(s[kc][1]), F2U(s[kc][3]) };
                unsigned b[4][2];
                #pragma unroll
                for (int dt = 0; dt < 4; dt++) {
                    b[dt][0] = F2U(sV[(kc*8 + t)*36 + dt*8 + g]);
                    b[dt][1] = F2U(sV[(kc*8 + t + 4)*36 + dt*8 + g]);
                }
                #pragma unroll
                for (int dt = 0; dt < 4; dt++) mma8(o[dt], a, b[dt]);
            }
        }
    }

    #pragma unroll
    for (int msk = 1; msk < 4; msk <<= 1) {
        l0 += __shfl_xor_sync(0xffffffffu, l0, msk);
        l1 += __shfl_xor_sync(0xffffffffu, l1, msk);
    }
    float inv0 = 1.f / l0, inv1 = 1.f / l1;
    int r = q0 + qr;
    #pragma unroll
    for (int dt = 0; dt < 4; dt++) {
        int col = h*32 + dt*8 + t*2;
        *(float2*)&out[(size_t)r*256 + col]     = make_float2(tfr(o[dt][0]*inv0), tfr(o[dt][1]*inv0));
        *(float2*)&out[(size_t)(r+8)*256 + col] = make_float2(tfr(o[dt][2]*inv1), tfr(o[dt][3]*inv1));
    }
}

// ---- graph ----
__global__ void k_deg(const void* __restrict__ edges, const float* __restrict__ ew) {
    int e = blockIdx.x*blockDim.x + threadIdx.x;
    if (e >= NEDGE) return;
    int r, c; get_edge(edges, e, r, c);
    float w = ew[e];
    atomicAdd(&d_deg[r], w);  atomicAdd(&d_deg[c], w);
    atomicAdd(&d_rowcnt[r], 1); atomicAdd(&d_rowcnt[c], 1);
}
__global__ __launch_bounds__(1024) void k_scan() {
    __shared__ int s[1024];
    int tid = threadIdx.x;
    #pragma unroll
    for (int j = 0; j < 4; j++) {
        int i = tid*4 + j;
        d_dinv[i] = rsqrtf(d_deg[i] + 1e-6f);
    }
    int c0 = d_rowcnt[tid*4], c1 = d_rowcnt[tid*4+1], c2 = d_rowcnt[tid*4+2], c3 = d_rowcnt[tid*4+3];
    int p0 = c0, p1 = p0+c1, p2 = p1+c2, p3 = p2+c3;
    s[tid] = p3;
    __syncthreads();
    for (int off = 1; off < 1024; off <<= 1) {
        int v = (tid >= off) ? s[tid-off] : 0;
        __syncthreads(); s[tid] += v; __syncthreads();
    }
    int excl = s[tid] - p3;
    d_rowptr[tid*4] = excl; d_rowptr[tid*4+1] = excl+p0;
    d_rowptr[tid*4+2] = excl+p1; d_rowptr[tid*4+3] = excl+p2;
    if (tid == 1023) d_rowptr[NNODES] = s[1023];
}
__global__ void k_fill(const void* __restrict__ edges, const float* __restrict__ ew) {
    int e = blockIdx.x*blockDim.x + threadIdx.x;
    if (e >= NEDGE) return;
    int r, c; get_edge(edges, e, r, c);
    float w = ew[e];
    int p1 = d_rowptr[r] + atomicAdd(&d_fillcnt[r], 1);
    d_col[p1] = c;  d_coef[p1] = w * d_dinv[c];
    int p2 = d_rowptr[c] + atomicAdd(&d_fillcnt[c], 1);
    d_col[p2] = r;  d_coef[p2] = w * d_dinv[r];
}
__global__ __launch_bounds__(256) void k_spmm(const float* __restrict__ xin,
                                              float* __restrict__ xout) {
    int n = blockIdx.x, t = threadIdx.x;
    int s = d_rowptr[n], e = d_rowptr[n+1];
    float a0 = 0.f, a1 = 0.f, a2 = 0.f, a3 = 0.f;
    int j = s;
    for (; j + 4 <= e; j += 4) {
        int   c0 = __ldg(&d_col[j]),   c1 = __ldg(&d_col[j+1]);
        int   c2 = __ldg(&d_col[j+2]), c3 = __ldg(&d_col[j+3]);
        float f0 = __ldg(&d_coef[j]),  f1 = __ldg(&d_coef[j+1]);
        float f2 = __ldg(&d_coef[j+2]),f3 = __ldg(&d_coef[j+3]);
        a0 += f0 * xin[(size_t)c0*HIDD + t];
        a1 += f1 * xin[(size_t)c1*HIDD + t];
        a2 += f2 * xin[(size_t)c2*HIDD + t];
        a3 += f3 * xin[(size_t)c3*HIDD + t];
    }
    for (; j < e; j++)
        a0 += __ldg(&d_coef[j]) * xin[(size_t)__ldg(&d_col[j])*HIDD + t];
    xout[(size_t)n*HIDD + t] = tfr(d_dinv[n] * ((a0+a1)+(a2+a3)));
}

extern "C" void kernel_launch(void* const* d_in, const int* in_sizes, int n_in,
                              void* d_out, int out_size) {
    const float* node_feats = (const float*)d_in[0];
    const void*  edges      = d_in[1];
    const float* ew         = (const float*)d_in[2];
    const float* conv_b  = (const float*)d_in[4];
    const float* bn_g    = (const float*)d_in[5];
    const float* bn_b    = (const float*)d_in[6];
    const float* bn_m    = (const float*)d_in[7];
    const float* bn_v    = (const float*)d_in[8];
    const float* qkv_b   = (const float*)d_in[10];
    const float* proj_b  = (const float*)d_in[12];
    const float* gcn1_b  = (const float*)d_in[14];
    const float* ln1_g   = (const float*)d_in[15];
    const float* ln1_b   = (const float*)d_in[16];
    const float* gcn2_b  = (const float*)d_in[18];
    const float* ln2_g   = (const float*)d_in[19];
    const float* ln2_b   = (const float*)d_in[20];
    const float* sc_b    = (const float*)d_in[22];
    float* out = (float*)d_out;

    float *p_x,*p_qkv,*p_att,*p_x2,*p_s1,*p_g1,*p_s2;
    float *p_wq,*p_wp,*p_w1,*p_w2,*p_ws,*p_wc;
    cudaGetSymbolAddress((void**)&p_x, d_x);   cudaGetSymbolAddress((void**)&p_qkv, d_qkv);
    cudaGetSymbolAddress((void**)&p_att, d_att); cudaGetSymbolAddress((void**)&p_x2, d_x2);
    cudaGetSymbolAddress((void**)&p_s1, d_s1); cudaGetSymbolAddress((void**)&p_g1, d_g1);
    cudaGetSymbolAddress((void**)&p_s2, d_s2);
    cudaGetSymbolAddress((void**)&p_wq, d_wq); cudaGetSymbolAddress((void**)&p_wp, d_wp);
    cudaGetSymbolAddress((void**)&p_w1, d_w1); cudaGetSymbolAddress((void**)&p_w2, d_w2);
    cudaGetSymbolAddress((void**)&p_ws, d_ws); cudaGetSymbolAddress((void**)&p_wc, d_wc);

    static cudaStream_t s1;
    static cudaEvent_t evF1, evJ1, evF2, evJ2;
    static int done = 0;
    if (!done) {
        cudaFuncSetAttribute((const void*)k_gemm_t<4,128,true,false>,  cudaFuncAttributeMaxDynamicSharedMemorySize, GEMM_SMEM(4,128));
        cudaFuncSetAttribute((const void*)k_gemm_t<2,128,false,false>, cudaFuncAttributeMaxDynamicSharedMemorySize, GEMM_SMEM(2,128));
        cudaFuncSetAttribute((const void*)k_gemm_t<1,256,true,true>,   cudaFuncAttributeMaxDynamicSharedMemorySize, GEMM_SMEM(1,256));
        cudaFuncSetAttribute((const void*)k_gemm_t<1,128,false,true>,  cudaFuncAttributeMaxDynamicSharedMemorySize, GEMM_SMEM(1,128));
        cudaFuncSetAttribute((const void*)k_gemm_t<1,128,false,false>, cudaFuncAttributeMaxDynamicSharedMemorySize, GEMM_SMEM(1,128));
        cudaFuncSetAttribute(k_dimreduce_t, cudaFuncAttributeMaxDynamicSharedMemorySize, DIMR_SMEM_BYTES);
        cudaFuncSetAttribute(k_attn_t,      cudaFuncAttributeMaxDynamicSharedMemorySize, ATT_SMEM_BYTES);
        cudaStreamCreateWithFlags(&s1, cudaStreamNonBlocking);
        cudaEventCreateWithFlags(&evF1, cudaEventDisableTiming);
        cudaEventCreateWithFlags(&evJ1, cudaEventDisableTiming);
        cudaEventCreateWithFlags(&evF2, cudaEventDisableTiming);
        cudaEventCreateWithFlags(&evJ2, cudaEventDisableTiming);
        done = 1;
    }

    // ---- fork: graph-structure chain on side stream ----
    cudaEventRecord(evF1, 0);
    cudaStreamWaitEvent(s1, evF1, 0);
    k_init<<<16, 256, 0, s1>>>((const int*)edges);
    k_deg <<<NEDGE/256, 256, 0, s1>>>(edges, ew);
    k_scan<<<1, 1024, 0, s1>>>();
    k_fill<<<NEDGE/256, 256, 0, s1>>>(edges, ew);
    cudaEventRecord(evJ1, s1);

    // ---- main chain ----
    k_round_all<<<(RW_TOT+255)/256, 256>>>((const float*)d_in[9], (const float*)d_in[11],
        (const float*)d_in[13], (const float*)d_in[17], (const float*)d_in[21], (const float*)d_in[3]);

    k_dimreduce_t<<<dim3(2, 512), 256, DIMR_SMEM_BYTES>>>(node_feats, p_wc, conv_b, bn_g, bn_b, bn_m, bn_v);

    k_gemm_t<4,128,true,false><<<dim3(6, 32), 256, GEMM_SMEM(4,128)>>>(
        p_x, p_wq, qkv_b, nullptr, nullptr, nullptr, p_qkv, 768);

    k_attn_t<<<dim3(32, NHEADS), 256, ATT_SMEM_BYTES>>>(p_qkv, p_att);

    k_gemm_t<2,128,false,false><<<dim3(2, 64), 256, GEMM_SMEM(2,128)>>>(
        p_att, p_wp, proj_b, nullptr, nullptr, nullptr, p_x2, 256);

    // join graph chain before first SpMM
    cudaStreamWaitEvent(0, evJ1, 0);

    k_spmm<<<NNODES, 256>>>(p_x2, p_s1);
    k_gemm_t<1,256,true,true><<<dim3(1, 128), 256, GEMM_SMEM(1,256)>>>(
        p_s1, p_w1, gcn1_b, nullptr, ln1_g, ln1_b, p_g1, 256);

    // ---- fork: shortcut GEMM (needs only g1) runs parallel with spmm2 ----
    cudaEventRecord(evF2, 0);
    cudaStreamWaitEvent(s1, evF2, 0);
    k_gemm_t<1,128,false,false><<<dim3(1, 128), 256, GEMM_SMEM(1,128), s1>>>(
        p_g1, p_ws, sc_b, nullptr, nullptr, nullptr, out, 128);
    cudaEventRecord(evJ2, s1);

    k_spmm<<<NNODES, 256>>>(p_g1, p_s2);

    // join shortcut; gcn2 fused LN+ReLU adds resid (=shortcut in `out`) and
    // writes the final output in place.
    cudaStreamWaitEvent(0, evJ2, 0);
    k_gemm_t<1,128,false,true><<<dim3(1, 128), 256, GEMM_SMEM(1,128)>>>(
        p_s2, p_w2, gcn2_b, out, ln2_g, ln2_b, out, 128);
}

// round 16
// speedup vs baseline: 1.0127x; 1.0003x over previous
#include <cuda_runtime.h>
#include <cstdint>
#include <math.h>

#define NNODES 4096
#define HIDD   256
#define NHEADS 8
#define NEDGE  65536
#define NDIR   (2*NEDGE)

__device__ float d_x   [NNODES*HIDD];
__device__ float d_qkv [NNODES*3*HIDD];
__device__ float d_att [NNODES*HIDD];
__device__ float d_x2  [NNODES*HIDD];
__device__ float d_s1  [NNODES*HIDD];
__device__ float d_g1  [NNODES*HIDD];
__device__ float d_s2  [NNODES*HIDD];
__device__ float d_deg [NNODES];
__device__ float d_dinv[NNODES];
__device__ int   d_rowcnt[NNODES];
__device__ int   d_fillcnt[NNODES];
__device__ int   d_rowptr[NNODES+1];
__device__ int   d_col [NDIR];
__device__ float d_coef[NDIR];
__device__ int   d_e64flag;
__device__ float d_wq[768*256];
__device__ float d_wp[256*256];
__device__ float d_w1[256*256];
__device__ float d_w2[128*256];
__device__ float d_ws[128*256];
__device__ float d_wc[256*256];

__device__ __forceinline__ unsigned f2tf(float x) {
    unsigned r; asm("cvt.rna.tf32.f32 %0, %1;" : "=r"(r) : "f"(x)); return r;
}
__device__ __forceinline__ float tfr(float x) { return __uint_as_float(f2tf(x)); }
__device__ __forceinline__ unsigned F2U(float x) { return __float_as_uint(x); }
__device__ __forceinline__ void mma8(float* d, const unsigned* a, const unsigned* b) {
    asm volatile("mma.sync.aligned.m16n8k8.row.col.f32.tf32.tf32.f32 "
        "{%0,%1,%2,%3}, {%4,%5,%6,%7}, {%8,%9}, {%0,%1,%2,%3};"
        : "+f"(d[0]), "+f"(d[1]), "+f"(d[2]), "+f"(d[3])
        : "r"(a[0]), "r"(a[1]), "r"(a[2]), "r"(a[3]), "r"(b[0]), "r"(b[1]));
}
__device__ __forceinline__ void cpa16(unsigned dst, const float* src) {
    asm volatile("cp.async.cg.shared.global [%0], [%1], 16;" :: "r"(dst), "l"(src));
}
__device__ __forceinline__ void cpa_commit() { asm volatile("cp.async.commit_group;"); }
__device__ __forceinline__ void cpa_wait1()  { asm volatile("cp.async.wait_group 1;"); }
__device__ __forceinline__ void cpa_wait0()  { asm volatile("cp.async.wait_group 0;"); }
__device__ __forceinline__ unsigned smem_u32(const void* p) {
    return (unsigned)__cvta_generic_to_shared(p);
}

// ---- misc ----
__global__ void k_init(const int* __restrict__ e) {
    int i = blockIdx.x*256 + threadIdx.x;
    if (i < NNODES) { d_deg[i]=0.f; d_rowcnt[i]=0; d_fillcnt[i]=0; }
    if (blockIdx.x == 0 && threadIdx.x == 0) {
        int z = 0;
        #pragma unroll
        for (int j = 1; j < 16; j += 2) z |= e[j];
        d_e64flag = (z == 0) ? 1 : 0;
    }
}
// conv weight only (blocks dimreduce)
__global__ void k_round_wc(const float* __restrict__ cw) {
    int j = blockIdx.x*256 + threadIdx.x;
    if (j < 65536) d_wc[j] = tfr(cw[j]);
}
// remaining weights (side stream, must finish before qkv)
#define RR_TOT 393216
__global__ void k_round_rest(const float* __restrict__ qw, const float* __restrict__ pw,
                             const float* __restrict__ w1, const float* __restrict__ w2,
                             const float* __restrict__ sw) {
    int j = blockIdx.x*256 + threadIdx.x;
    if (j >= RR_TOT) return;
    if (j < 196608) { d_wq[j] = tfr(qw[j]); return; }  j -= 196608;
    if (j < 65536)  { d_wp[j] = tfr(pw[j]); return; }  j -= 65536;
    if (j < 65536)  { d_w1[j] = tfr(w1[j]); return; }  j -= 65536;
    if (j < 32768)  { d_w2[j] = tfr(w2[j]); return; }  j -= 32768;
    d_ws[j] = tfr(sw[j]);
}
__device__ __forceinline__ void get_edge(const void* edges, int e, int& r, int& c) {
    if (d_e64flag) { const long long* p = (const long long*)edges; r = (int)p[2*e]; c = (int)p[2*e+1]; }
    else           { const int* p = (const int*)edges;             r = p[2*e];      c = p[2*e+1]; }
}

// ---- tf32 GEMM: C[M,N] = A[M,256] @ B[N,256]^T + bias (+resid) (+LN+ReLU) --
template<int MT, int BN, bool RND, bool LN>
__global__ __launch_bounds__(256,2) void k_gemm_t(
    const float* __restrict__ A, const float* __restrict__ B,
    const float* __restrict__ bias, const float* __restrict__ resid,
    const float* __restrict__ lnG, const float* __restrict__ lnB,
    float* __restrict__ C, int N)
{
    extern __shared__ float fs[];
    const int BM  = MT*32;
    const int NT  = BN/32;
    const int ASZ = BM*36;
    const int STG = ASZ + BN*36;
    const int NST = (BN == 256) ? 2 : 3;
    unsigned sbase = smem_u32(fs);
    const int K = 256;
    int m0 = blockIdx.y*BM, n0 = blockIdx.x*BN;
    int tid = threadIdx.x;
    int warp = tid >> 5, lane = tid & 31;
    int wy = warp >> 2, wx = warp & 3;
    int g = lane >> 2, t = lane & 3;
    float acc[MT][NT][4] = {};
    int lr = tid >> 3, lkv = (tid & 7)*4;

    auto issue = [&](int k0, int st) {
        #pragma unroll
        for (int j = 0; j < MT; j++) {
            int r = lr + j*32;
            cpa16(sbase + (st*STG + r*36 + lkv)*4, &A[(size_t)(m0+r)*K + k0 + lkv]);
        }
        #pragma unroll
        for (int j = 0; j < BN/32; j++) {
            int r = lr + j*32;
            cpa16(sbase + (st*STG + ASZ + r*36 + lkv)*4, &B[(size_t)(n0+r)*K + k0 + lkv]);
        }
        cpa_commit();
    };

    issue(0, 0);
    if (NST == 3) issue(32, 1);
    for (int i = 0; i < 8; i++) {
        if (NST == 3) { if (i < 7) cpa_wait1(); else cpa_wait0(); }
        else cpa_wait0();
        __syncthreads();
        if (i < 8 - (NST-1)) issue((i+NST-1)*32, (i+NST-1)%NST);
        const float* sA = fs + (i%NST)*STG;
        const float* sB = sA + ASZ;
        #pragma unroll
        for (int kc = 0; kc < 4; kc++) {
            unsigned a[MT][4], b[NT][2];
            #pragma unroll
            for (int mt = 0; mt < MT; mt++) {
                int r = wy*(16*MT) + mt*16 + g;
                a[mt][0] = F2U(sA[r*36 + kc*8 + t]);
                a[mt][1] = F2U(sA[(r+8)*36 + kc*8 + t]);
                a[mt][2] = F2U(sA[r*36 + kc*8 + t + 4]);
                a[mt][3] = F2U(sA[(r+8)*36 + kc*8 + t + 4]);
            }
            #pragma unroll
            for (int nt = 0; nt < NT; nt++) {
                int r = wx*(8*NT) + nt*8 + g;
                b[nt][0] = F2U(sB[r*36 + kc*8 + t]);
                b[nt][1] = F2U(sB[r*36 + kc*8 + t + 4]);
            }
            #pragma unroll
            for (int mt = 0; mt < MT; mt++)
                #pragma unroll
                for (int nt = 0; nt < NT; nt++)
                    mma8(acc[mt][nt], a[mt], b[nt]);
        }
        __syncthreads();
    }

    if (LN) {
        float* redS = fs;
        float* redQ = fs + BM*4;
        #pragma unroll
        for (int mt = 0; mt < MT; mt++) {
            float sl = 0.f, ql = 0.f, sh = 0.f, qh = 0.f;
            #pragma unroll
            for (int nt = 0; nt < NT; nt++) {
                int col = n0 + wx*(8*NT) + nt*8 + t*2;
                float2 bi = *(const float2*)&bias[col];
                float v0 = acc[mt][nt][0]+bi.x, v1 = acc[mt][nt][1]+bi.y;
                float w0 = acc[mt][nt][2]+bi.x, w1 = acc[mt][nt][3]+bi.y;
                acc[mt][nt][0]=v0; acc[mt][nt][1]=v1; acc[mt][nt][2]=w0; acc[mt][nt][3]=w1;
                sl += v0+v1; ql += v0*v0+v1*v1;
                sh += w0+w1; qh += w0*w0+w1*w1;
            }
            #pragma unroll
            for (int msk = 1; msk < 4; msk <<= 1) {
                sl += __shfl_xor_sync(0xffffffffu, sl, msk);
                ql += __shfl_xor_sync(0xffffffffu, ql, msk);
                sh += __shfl_xor_sync(0xffffffffu, sh, msk);
                qh += __shfl_xor_sync(0xffffffffu, qh, msk);
            }
            if (t == 0) {
                int rl = wy*(16*MT) + mt*16 + g;
                redS[rl*4 + wx] = sl;     redQ[rl*4 + wx] = ql;
                redS[(rl+8)*4 + wx] = sh; redQ[(rl+8)*4 + wx] = qh;
            }
        }
        __syncthreads();
        #pragma unroll
        for (int mt = 0; mt < MT; mt++) {
            int rl = wy*(16*MT) + mt*16 + g;
            float S0 = redS[rl*4]+redS[rl*4+1]+redS[rl*4+2]+redS[rl*4+3];
            float Q0 = redQ[rl*4]+redQ[rl*4+1]+redQ[rl*4+2]+redQ[rl*4+3];
            float S1 = redS[(rl+8)*4]+redS[(rl+8)*4+1]+redS[(rl+8)*4+2]+redS[(rl+8)*4+3];
            float Q1 = redQ[(rl+8)*4]+redQ[(rl+8)*4+1]+redQ[(rl+8)*4+2]+redQ[(rl+8)*4+3];
            float mu0 = S0/BN, r0v = rsqrtf(Q0/BN - mu0*mu0 + 1e-5f);
            float mu1 = S1/BN, r1v = rsqrtf(Q1/BN - mu1*mu1 + 1e-5f);
            int row = m0 + rl;
            #pragma unroll
            for (int nt = 0; nt < NT; nt++) {
                int col = n0 + wx*(8*NT) + nt*8 + t*2;
                float2 gg = *(const float2*)&lnG[col];
                float2 bb = *(const float2*)&lnB[col];
                float o00 = fmaxf((acc[mt][nt][0]-mu0)*r0v*gg.x + bb.x, 0.f);
                float o01 = fmaxf((acc[mt][nt][1]-mu0)*r0v*gg.y + bb.y, 0.f);
                float o10 = fmaxf((acc[mt][nt][2]-mu1)*r1v*gg.x + bb.x, 0.f);
                float o11 = fmaxf((acc[mt][nt][3]-mu1)*r1v*gg.y + bb.y, 0.f);
                if (resid) {
                    float2 r0 = *(const float2*)&resid[(size_t)row*N + col];
                    float2 r1 = *(const float2*)&resid[(size_t)(row+8)*N + col];
                    o00 += r0.x; o01 += r0.y; o10 += r1.x; o11 += r1.y;
                }
                if (RND) { o00=tfr(o00); o01=tfr(o01); o10=tfr(o10); o11=tfr(o11); }
                *(float2*)&C[(size_t)row*N + col]     = make_float2(o00, o01);
                *(float2*)&C[(size_t)(row+8)*N + col] = make_float2(o10, o11);
            }
        }
    } else {
        #pragma unroll
        for (int mt = 0; mt < MT; mt++) {
            #pragma unroll
            for (int nt = 0; nt < NT; nt++) {
                int row = m0 + wy*(16*MT) + mt*16 + g;
                int col = n0 + wx*(8*NT) + nt*8 + t*2;
                float2 bi = *(const float2*)&bias[col];
                float o00 = acc[mt][nt][0]+bi.x, o01 = acc[mt][nt][1]+bi.y;
                float o10 = acc[mt][nt][2]+bi.x, o11 = acc[mt][nt][3]+bi.y;
                if (resid) {
                    float2 r0 = *(const float2*)&resid[(size_t)row*N + col];
                    float2 r1 = *(const float2*)&resid[(size_t)(row+8)*N + col];
                    o00 += r0.x; o01 += r0.y; o10 += r1.x; o11 += r1.y;
                }
                if (RND) { o00=tfr(o00); o01=tfr(o01); o10=tfr(o10); o11=tfr(o11); }
                *(float2*)&C[(size_t)row*N + col]     = make_float2(o00, o01);
                *(float2*)&C[(size_t)(row+8)*N + col] = make_float2(o10, o11);
            }
        }
    }
}
#define GEMM_SMEM(MT,BN) (((BN)==256?2:3)*(((MT)*32+(BN))*36)*4)

// ---- dim_reduce fat-tile GEMM: CTA 128x256, warp tile 64x64 (MT=4,NT=8) ----
#define DW_STG (32*132 + 256*36)
#define DIMW_SMEM_BYTES (3*DW_STG*4)
__global__ __launch_bounds__(256,1) void k_dimreduce_w(
    const float* __restrict__ feats, const float* __restrict__ W,
    const float* __restrict__ cb, const float* __restrict__ gamma,
    const float* __restrict__ beta, const float* __restrict__ mean,
    const float* __restrict__ var)
{
    extern __shared__ float fs[];
    unsigned sbase = smem_u32(fs);
    int m0 = blockIdx.y*128;
    int nb = m0 >> 4;
    int tid = threadIdx.x;
    int warp = tid >> 5, lane = tid & 31;
    int wy = warp >> 2, wx = warp & 3;
    int g = lane >> 2, t = lane & 3;
    float acc[4][8][4] = {};
    int lhw = (tid & 3)*4, lc = (tid >> 2) & 31, lnd = tid >> 7;
    int lr = tid >> 3, lkv = (tid & 7)*4;

    auto issue = [&](int k0, int st) {
        #pragma unroll
        for (int j = 0; j < 4; j++) {
            int nd = lnd + j*2;
            cpa16(sbase + (st*DW_STG + lc*132 + nd*16 + lhw)*4,
                  &feats[(size_t)(nb+nd)*4096 + (k0+lc)*16 + lhw]);
        }
        #pragma unroll
        for (int j = 0; j < 8; j++) {
            int r = lr + j*32;
            cpa16(sbase + (st*DW_STG + 4224 + r*36 + lkv)*4, &W[(size_t)r*256 + k0 + lkv]);
        }
        cpa_commit();
    };

    issue(0, 0); issue(32, 1);
    for (int i = 0; i < 8; i++) {
        if (i < 7) cpa_wait1(); else cpa_wait0();
        __syncthreads();
        if (i < 6) issue((i+2)*32, (i+2)%3);
        const float* sAT = fs + (i%3)*DW_STG;
        const float* sB  = sAT + 4224;
        #pragma unroll
        for (int kc = 0; kc < 4; kc++) {
            unsigned a[4][4], b[8][2];
            #pragma unroll
            for (int mt = 0; mt < 4; mt++) {
                int r = wy*64 + mt*16 + g;
                a[mt][0] = f2tf(sAT[(kc*8 + t)*132 + r]);
                a[mt][1] = f2tf(sAT[(kc*8 + t)*132 + r + 8]);
                a[mt][2] = f2tf(sAT[(kc*8 + t + 4)*132 + r]);
                a[mt][3] = f2tf(sAT[(kc*8 + t + 4)*132 + r + 8]);
            }
            #pragma unroll
            for (int nt = 0; nt < 8; nt++) {
                int r = wx*64 + nt*8 + g;
                b[nt][0] = F2U(sB[r*36 + kc*8 + t]);
                b[nt][1] = F2U(sB[r*36 + kc*8 + t + 4]);
            }
            #pragma unroll
            for (int mt = 0; mt < 4; mt++)
                #pragma unroll
                for (int nt = 0; nt < 8; nt++)
                    mma8(acc[mt][nt], a[mt], b[nt]);
        }
        __syncthreads();
    }
    #pragma unroll
    for (int mt = 0; mt < 4; mt++) {
        int node = nb + wy*4 + mt;
        #pragma unroll
        for (int nt = 0; nt < 8; nt++) {
            int col = wx*64 + nt*8 + t*2;
            float s0 = gamma[col]   * rsqrtf(var[col]   + 1e-5f);
            float s1 = gamma[col+1] * rsqrtf(var[col+1] + 1e-5f);
            float c0 = (cb[col]   - mean[col])  *s0 + beta[col];
            float c1 = (cb[col+1] - mean[col+1])*s1 + beta[col+1];
            float sum0 = fmaxf(acc[mt][nt][0]*s0 + c0, 0.f) + fmaxf(acc[mt][nt][2]*s0 + c0, 0.f);
            float sum1 = fmaxf(acc[mt][nt][1]*s1 + c1, 0.f) + fmaxf(acc[mt][nt][3]*s1 + c1, 0.f);
            #pragma unroll
            for (int msk = 4; msk < 32; msk <<= 1) {
                sum0 += __shfl_xor_sync(0xffffffffu, sum0, msk);
                sum1 += __shfl_xor_sync(0xffffffffu, sum1, msk);
            }
            if (g == 0) {
                d_x[node*HIDD + col]   = tfr(sum0 * (1.f/16.f));
                d_x[node*HIDD + col+1] = tfr(sum1 * (1.f/16.f));
            }
        }
    }
}

// ---- flash attention: q-tile 128, KV-tile 128 (two 64-key halves), 2-stage -
#define AQ   0
#define AKV  4608
#define ASTG 9216
#define ATT_SMEM_BYTES ((AKV + 2*ASTG)*4)

__global__ __launch_bounds__(256,2) void k_attn_t(const float* __restrict__ qkv,
                                                  float* __restrict__ out)
{
    extern __shared__ float fs[];
    unsigned sbase = smem_u32(fs);
    int h  = blockIdx.y;
    int q0 = blockIdx.x * 128;
    int tid = threadIdx.x;
    int warp = tid >> 5, lane = tid & 31;
    int g = lane >> 2, t = lane & 3;
    const float scale = 0.17677669529663689f;   // 32^-0.5
    int lr = tid >> 3, lkv = (tid & 7)*4;
    int qr = warp*16 + g;

    #pragma unroll
    for (int j = 0; j < 4; j++) {
        int r = lr + j*32;
        float4 v = *(const float4*)&qkv[(size_t)(q0+r)*768 + h*32 + lkv];
        float* p = &fs[AQ + r*36 + lkv];
        p[0]=tfr(v.x*scale); p[1]=tfr(v.y*scale);
        p[2]=tfr(v.z*scale); p[3]=tfr(v.w*scale);
    }

    auto issue = [&](int kt) {
        unsigned kb = sbase + (AKV + (kt&1)*ASTG)*4;
        #pragma unroll
        for (int j = 0; j < 4; j++) {
            int r = lr + j*32;
            int pr = (r & ~7) | (((r & 3) << 1) | ((r >> 2) & 1));  // K row permute
            const float* srcK = &qkv[(size_t)(kt*128+r)*768 + 256 + h*32 + lkv];
            cpa16(kb + (pr*36 + lkv)*4,          srcK);
            cpa16(kb + ((4608 + r*36) + lkv)*4,  srcK + 256);
        }
        cpa_commit();
    };

    issue(0);
    __syncthreads();

    unsigned qa[4][4];
    #pragma unroll
    for (int kc = 0; kc < 4; kc++) {
        qa[kc][0] = F2U(fs[AQ + qr*36 + kc*8 + t]);
        qa[kc][1] = F2U(fs[AQ + (qr+8)*36 + kc*8 + t]);
        qa[kc][2] = F2U(fs[AQ + qr*36 + kc*8 + t + 4]);
        qa[kc][3] = F2U(fs[AQ + (qr+8)*36 + kc*8 + t + 4]);
    }

    float l0 = 0.f, l1 = 0.f;
    float o[4][4] = {};

    for (int it = 0; it < 32; it++) {
        cpa_wait0();
        __syncthreads();
        if (it < 31) issue(it+1);
        const float* sKt = fs + AKV + (it&1)*ASTG;

        #pragma unroll
        for (int half = 0; half < 2; half++) {
            const float* sK = sKt + half*64*36;
            const float* sV = sKt + 4608 + half*64*36;

            float s[8][4] = {};
            #pragma unroll
            for (int kc = 0; kc < 4; kc++) {
                unsigned b[8][2];
                #pragma unroll
                for (int nt = 0; nt < 8; nt++) {
                    b[nt][0] = F2U(sK[(nt*8+g)*36 + kc*8 + t]);
                    b[nt][1] = F2U(sK[(nt*8+g)*36 + kc*8 + t + 4]);
                }
                #pragma unroll
                for (int nt = 0; nt < 8; nt++) mma8(s[nt], qa[kc], b[nt]);
            }

            #pragma unroll
            for (int nt = 0; nt < 8; nt++) {
                float e0 = __expf(s[nt][0]); l0 += e0; s[nt][0] = __uint_as_float(f2tf(e0));
                float e1 = __expf(s[nt][1]); l0 += e1; s[nt][1] = __uint_as_float(f2tf(e1));
                float e2 = __expf(s[nt][2]); l1 += e2; s[nt][2] = __uint_as_float(f2tf(e2));
                float e3 = __expf(s[nt][3]); l1 += e3; s[nt][3] = __uint_as_float(f2tf(e3));
            }

            #pragma unroll
            for (int kc = 0; kc < 8; kc++) {
                unsigned a[4] = { F2U(s[kc][0]), F2U(s[kc][2]), F2U(s[kc][1]), F2U(s[kc][3]) };
                unsigned b[4][2];
                #pragma unroll
                for (int dt = 0; dt < 4; dt++) {
                    b[dt][0] = F2U(sV[(kc*8 + t)*36 + dt*8 + g]);
                    b[dt][1] = F2U(sV[(kc*8 + t + 4)*36 + dt*8 + g]);
                }
                #pragma unroll
                for (int dt = 0; dt < 4; dt++) mma8(o[dt], a, b[dt]);
            }
        }
    }

    #pragma unroll
    for (int msk = 1; msk < 4; msk <<= 1) {
        l0 += __shfl_xor_sync(0xffffffffu, l0, msk);
        l1 += __shfl_xor_sync(0xffffffffu, l1, msk);
    }
    float inv0 = 1.f / l0, inv1 = 1.f / l1;
    int r = q0 + qr;
    #pragma unroll
    for (int dt = 0; dt < 4; dt++) {
        int col = h*32 + dt*8 + t*2;
        *(float2*)&out[(size_t)r*256 + col]     = make_float2(tfr(o[dt][0]*inv0), tfr(o[dt][1]*inv0));
        *(float2*)&out[(size_t)(r+8)*256 + col] = make_float2(tfr(o[dt][2]*inv1), tfr(o[dt][3]*inv1));
    }
}

// ---- graph ----
__global__ void k_deg(const void* __restrict__ edges, const float* __restrict__ ew) {
    int e = blockIdx.x*blockDim.x + threadIdx.x;
    if (e >= NEDGE) return;
    int r, c; get_edge(edges, e, r, c);
    float w = ew[e];
    atomicAdd(&d_deg[r], w);  atomicAdd(&d_deg[c], w);
    atomicAdd(&d_rowcnt[r], 1); atomicAdd(&d_rowcnt[c], 1);
}
__global__ __launch_bounds__(1024) void k_scan() {
    __shared__ int s[1024];
    int tid = threadIdx.x;
    #pragma unroll
    for (int j = 0; j < 4; j++) {
        int i = tid*4 + j;
        d_dinv[i] = rsqrtf(d_deg[i] + 1e-6f);
    }
    int c0 = d_rowcnt[tid*4], c1 = d_rowcnt[tid*4+1], c2 = d_rowcnt[tid*4+2], c3 = d_rowcnt[tid*4+3];
    int p0 = c0, p1 = p0+c1, p2 = p1+c2, p3 = p2+c3;
    s[tid] = p3;
    __syncthreads();
    for (int off = 1; off < 1024; off <<= 1) {
        int v = (tid >= off) ? s[tid-off] : 0;
        __syncthreads(); s[tid] += v; __syncthreads();
    }
    int excl = s[tid] - p3;
    d_rowptr[tid*4] = excl; d_rowptr[tid*4+1] = excl+p0;
    d_rowptr[tid*4+2] = excl+p1; d_rowptr[tid*4+3] = excl+p2;
    if (tid == 1023) d_rowptr[NNODES] = s[1023];
}
__global__ void k_fill(const void* __restrict__ edges, const float* __restrict__ ew) {
    int e = blockIdx.x*blockDim.x + threadIdx.x;
    if (e >= NEDGE) return;
    int r, c; get_edge(edges, e, r, c);
    float w = ew[e];
    int p1 = d_rowptr[r] + atomicAdd(&d_fillcnt[r], 1);
    d_col[p1] = c;  d_coef[p1] = w * d_dinv[c];
    int p2 = d_rowptr[c] + atomicAdd(&d_fillcnt[c], 1);
    d_col[p2] = r;  d_coef[p2] = w * d_dinv[r];
}
__global__ __launch_bounds__(256) void k_spmm(const float* __restrict__ xin,
                                              float* __restrict__ xout) {
    int n = blockIdx.x, t = threadIdx.x;
    int s = d_rowptr[n], e = d_rowptr[n+1];
    float a0 = 0.f, a1 = 0.f, a2 = 0.f, a3 = 0.f;
    int j = s;
    for (; j + 4 <= e; j += 4) {
        int   c0 = __ldg(&d_col[j]),   c1 = __ldg(&d_col[j+1]);
        int   c2 = __ldg(&d_col[j+2]), c3 = __ldg(&d_col[j+3]);
        float f0 = __ldg(&d_coef[j]),  f1 = __ldg(&d_coef[j+1]);
        float f2 = __ldg(&d_coef[j+2]),f3 = __ldg(&d_coef[j+3]);
        a0 += f0 * xin[(size_t)c0*HIDD + t];
        a1 += f1 * xin[(size_t)c1*HIDD + t];
        a2 += f2 * xin[(size_t)c2*HIDD + t];
        a3 += f3 * xin[(size_t)c3*HIDD + t];
    }
    for (; j < e; j++)
        a0 += __ldg(&d_coef[j]) * xin[(size_t)__ldg(&d_col[j])*HIDD + t];
    xout[(size_t)n*HIDD + t] = tfr(d_dinv[n] * ((a0+a1)+(a2+a3)));
}

extern "C" void kernel_launch(void* const* d_in, const int* in_sizes, int n_in,
                              void* d_out, int out_size) {
    const float* node_feats = (const float*)d_in[0];
    const void*  edges      = d_in[1];
    const float* ew         = (const float*)d_in[2];
    const float* conv_b  = (const float*)d_in[4];
    const float* bn_g    = (const float*)d_in[5];
    const float* bn_b    = (const float*)d_in[6];
    const float* bn_m    = (const float*)d_in[7];
    const float* bn_v    = (const float*)d_in[8];
    const float* qkv_b   = (const float*)d_in[10];
    const float* proj_b  = (const float*)d_in[12];
    const float* gcn1_b  = (const float*)d_in[14];
    const float* ln1_g   = (const float*)d_in[15];
    const float* ln1_b   = (const float*)d_in[16];
    const float* gcn2_b  = (const float*)d_in[18];
    const float* ln2_g   = (const float*)d_in[19];
    const float* ln2_b   = (const float*)d_in[20];
    const float* sc_b    = (const float*)d_in[22];
    float* out = (float*)d_out;

    float *p_x,*p_qkv,*p_att,*p_x2,*p_s1,*p_g1,*p_s2;
    float *p_wq,*p_wp,*p_w1,*p_w2,*p_ws,*p_wc;
    cudaGetSymbolAddress((void**)&p_x, d_x);   cudaGetSymbolAddress((void**)&p_qkv, d_qkv);
    cudaGetSymbolAddress((void**)&p_att, d_att); cudaGetSymbolAddress((void**)&p_x2, d_x2);
    cudaGetSymbolAddress((void**)&p_s1, d_s1); cudaGetSymbolAddress((void**)&p_g1, d_g1);
    cudaGetSymbolAddress((void**)&p_s2, d_s2);
    cudaGetSymbolAddress((void**)&p_wq, d_wq); cudaGetSymbolAddress((void**)&p_wp, d_wp);
    cudaGetSymbolAddress((void**)&p_w1, d_w1); cudaGetSymbolAddress((void**)&p_w2, d_w2);
    cudaGetSymbolAddress((void**)&p_ws, d_ws); cudaGetSymbolAddress((void**)&p_wc, d_wc);

    static cudaStream_t s1;
    static cudaEvent_t evF1, evJ1, evF2, evJ2, evW;
    static int done = 0;
    if (!done) {
        cudaFuncSetAttribute((const void*)k_gemm_t<4,128,true,false>,  cudaFuncAttributeMaxDynamicSharedMemorySize, GEMM_SMEM(4,128));
        cudaFuncSetAttribute((const void*)k_gemm_t<2,128,false,false>, cudaFuncAttributeMaxDynamicSharedMemorySize, GEMM_SMEM(2,128));
        cudaFuncSetAttribute((const void*)k_gemm_t<1,256,true,true>,   cudaFuncAttributeMaxDynamicSharedMemorySize, GEMM_SMEM(1,256));
        cudaFuncSetAttribute((const void*)k_gemm_t<1,128,false,true>,  cudaFuncAttributeMaxDynamicSharedMemorySize, GEMM_SMEM(1,128));
        cudaFuncSetAttribute((const void*)k_gemm_t<1,128,false,false>, cudaFuncAttributeMaxDynamicSharedMemorySize, GEMM_SMEM(1,128));
        cudaFuncSetAttribute(k_dimreduce_w, cudaFuncAttributeMaxDynamicSharedMemorySize, DIMW_SMEM_BYTES);
        cudaFuncSetAttribute(k_attn_t,      cudaFuncAttributeMaxDynamicSharedMemorySize, ATT_SMEM_BYTES);
        cudaStreamCreateWithFlags(&s1, cudaStreamNonBlocking);
        cudaEventCreateWithFlags(&evF1, cudaEventDisableTiming);
        cudaEventCreateWithFlags(&evJ1, cudaEventDisableTiming);
        cudaEventCreateWithFlags(&evF2, cudaEventDisableTiming);
        cudaEventCreateWithFlags(&evJ2, cudaEventDisableTiming);
        cudaEventCreateWithFlags(&evW,  cudaEventDisableTiming);
        done = 1;
    }

    // ---- fork: weight rounding (rest) + graph-structure chain on side stream
    cudaEventRecord(evF1, 0);
    cudaStreamWaitEvent(s1, evF1, 0);
    k_round_rest<<<(RR_TOT+255)/256, 256, 0, s1>>>((const float*)d_in[9], (const float*)d_in[11],
        (const float*)d_in[13], (const float*)d_in[17], (const float*)d_in[21]);
    cudaEventRecord(evW, s1);
    k_init<<<16, 256, 0, s1>>>((const int*)edges);
    k_deg <<<NEDGE/256, 256, 0, s1>>>(edges, ew);
    k_scan<<<1, 1024, 0, s1>>>();
    k_fill<<<NEDGE/256, 256, 0, s1>>>(edges, ew);
    cudaEventRecord(evJ1, s1);

    // ---- main chain ----
    k_round_wc<<<256, 256>>>((const float*)d_in[3]);

    k_dimreduce_w<<<dim3(1, 512), 256, DIMW_SMEM_BYTES>>>(node_feats, p_wc, conv_b, bn_g, bn_b, bn_m, bn_v);

    cudaStreamWaitEvent(0, evW, 0);   // wq ready (long since)
    k_gemm_t<4,128,true,false><<<dim3(6, 32), 256, GEMM_SMEM(4,128)>>>(
        p_x, p_wq, qkv_b, nullptr, nullptr, nullptr, p_qkv, 768);

    k_attn_t<<<dim3(32, NHEADS), 256, ATT_SMEM_BYTES>>>(p_qkv, p_att);

    k_gemm_t<2,128,false,false><<<dim3(2, 64), 256, GEMM_SMEM(2,128)>>>(
        p_att, p_wp, proj_b, nullptr, nullptr, nullptr, p_x2, 256);

    cudaStreamWaitEvent(0, evJ1, 0);  // graph structure ready

    k_spmm<<<NNODES, 256>>>(p_x2, p_s1);
    k_gemm_t<1,256,true,true><<<dim3(1, 128), 256, GEMM_SMEM(1,256)>>>(
        p_s1, p_w1, gcn1_b, nullptr, ln1_g, ln1_b, p_g1, 256);

    // ---- fork: shortcut GEMM parallel with spmm2 ----
    cudaEventRecord(evF2, 0);
    cudaStreamWaitEvent(s1, evF2, 0);
    k_gemm_t<1,128,false,false><<<dim3(1, 128), 256, GEMM_SMEM(1,128), s1>>>(
        p_g1, p_ws, sc_b, nullptr, nullptr, nullptr, out, 128);
    cudaEventRecord(evJ2, s1);

    k_spmm<<<NNODES, 256>>>(p_g1, p_s2);

    cudaStreamWaitEvent(0, evJ2, 0);
    k_gemm_t<1,128,false,true><<<dim3(1, 128), 256, GEMM_SMEM(1,128)>>>(
        p_s2, p_w2, gcn2_b, out, ln2_g, ln2_b, out, 128);
}

// round 17
// speedup vs baseline: 1.0671x; 1.0537x over previous
#include <cuda_runtime.h>
#include <cstdint>
#include <math.h>

#define NNODES 4096
#define HIDD   256
#define NHEADS 8
#define NEDGE  65536
#define NDIR   (2*NEDGE)

__device__ float d_x   [NNODES*HIDD];
__device__ float d_qkv [NNODES*3*HIDD];
__device__ float d_att [NNODES*HIDD];
__device__ float d_x2  [NNODES*HIDD];
__device__ float d_s1  [NNODES*HIDD];
__device__ float d_g1  [NNODES*HIDD];
__device__ float d_s2  [NNODES*HIDD];
__device__ float d_deg [NNODES];
__device__ float d_dinv[NNODES];
__device__ int   d_rowcnt[NNODES];
__device__ int   d_fillcnt[NNODES];
__device__ int   d_rowptr[NNODES+1];
__device__ int   d_col [NDIR];
__device__ float d_coef[NDIR];
__device__ int   d_e64flag;
__device__ float d_wq[768*256];
__device__ float d_wp[256*256];
__device__ float d_w1[256*256];
__device__ float d_w2[128*256];
__device__ float d_ws[128*256];
__device__ float d_zero[256];   // zero-initialized

__device__ __forceinline__ unsigned f2tf(float x) {
    unsigned r; asm("cvt.rna.tf32.f32 %0, %1;" : "=r"(r) : "f"(x)); return r;
}
__device__ __forceinline__ float tfr(float x) { return __uint_as_float(f2tf(x)); }
__device__ __forceinline__ unsigned F2U(float x) { return __float_as_uint(x); }
__device__ __forceinline__ void mma8(float* d, const unsigned* a, const unsigned* b) {
    asm volatile("mma.sync.aligned.m16n8k8.row.col.f32.tf32.tf32.f32 "
        "{%0,%1,%2,%3}, {%4,%5,%6,%7}, {%8,%9}, {%0,%1,%2,%3};"
        : "+f"(d[0]), "+f"(d[1]), "+f"(d[2]), "+f"(d[3])
        : "r"(a[0]), "r"(a[1]), "r"(a[2]), "r"(a[3]), "r"(b[0]), "r"(b[1]));
}
__device__ __forceinline__ void cpa16(unsigned dst, const float* src) {
    asm volatile("cp.async.cg.shared.global [%0], [%1], 16;" :: "r"(dst), "l"(src));
}
__device__ __forceinline__ void cpa_commit() { asm volatile("cp.async.commit_group;"); }
__device__ __forceinline__ void cpa_wait1()  { asm volatile("cp.async.wait_group 1;"); }
__device__ __forceinline__ void cpa_wait0()  { asm volatile("cp.async.wait_group 0;"); }
__device__ __forceinline__ unsigned smem_u32(const void* p) {
    return (unsigned)__cvta_generic_to_shared(p);
}

// ---- misc ----
__global__ void k_init(const int* __restrict__ e) {
    int i = blockIdx.x*256 + threadIdx.x;
    if (i < NNODES) { d_deg[i]=0.f; d_rowcnt[i]=0; d_fillcnt[i]=0; }
    if (blockIdx.x == 0 && threadIdx.x == 0) {
        int z = 0;
        #pragma unroll
        for (int j = 1; j < 16; j += 2) z |= e[j];
        d_e64flag = (z == 0) ? 1 : 0;
    }
}
#define RR_TOT 393216
__global__ void k_round_rest(const float* __restrict__ qw, const float* __restrict__ pw,
                             const float* __restrict__ w1, const float* __restrict__ w2,
                             const float* __restrict__ sw) {
    int j = blockIdx.x*256 + threadIdx.x;
    if (j >= RR_TOT) return;
    if (j < 196608) { d_wq[j] = tfr(qw[j]); return; }  j -= 196608;
    if (j < 65536)  { d_wp[j] = tfr(pw[j]); return; }  j -= 65536;
    if (j < 65536)  { d_w1[j] = tfr(w1[j]); return; }  j -= 65536;
    if (j < 32768)  { d_w2[j] = tfr(w2[j]); return; }  j -= 32768;
    d_ws[j] = tfr(sw[j]);
}
__device__ __forceinline__ void get_edge(const void* edges, int e, int& r, int& c) {
    if (d_e64flag) { const long long* p = (const long long*)edges; r = (int)p[2*e]; c = (int)p[2*e+1]; }
    else           { const int* p = (const int*)edges;             r = p[2*e];      c = p[2*e+1]; }
}

// ---- tf32 GEMM: C[M,N] = A[M,256] @ B[N,256]^T + bias (+resid) ----
template<int MT, int BN, bool RND>
__global__ __launch_bounds__(256,2) void k_gemm_t(
    const float* __restrict__ A, const float* __restrict__ B,
    const float* __restrict__ bias, const float* __restrict__ resid,
    float* __restrict__ C, int N)
{
    extern __shared__ float fs[];
    const int BM  = MT*32;
    const int NT  = BN/32;
    const int ASZ = BM*36;
    const int STG = ASZ + BN*36;
    unsigned sbase = smem_u32(fs);
    const int K = 256;
    int m0 = blockIdx.y*BM, n0 = blockIdx.x*BN;
    int tid = threadIdx.x;
    int warp = tid >> 5, lane = tid & 31;
    int wy = warp >> 2, wx = warp & 3;
    int g = lane >> 2, t = lane & 3;
    float acc[MT][NT][4] = {};
    int lr = tid >> 3, lkv = (tid & 7)*4;

    auto issue = [&](int k0, int st) {
        #pragma unroll
        for (int j = 0; j < MT; j++) {
            int r = lr + j*32;
            cpa16(sbase + (st*STG + r*36 + lkv)*4, &A[(size_t)(m0+r)*K + k0 + lkv]);
        }
        #pragma unroll
        for (int j = 0; j < BN/32; j++) {
            int r = lr + j*32;
            cpa16(sbase + (st*STG + ASZ + r*36 + lkv)*4, &B[(size_t)(n0+r)*K + k0 + lkv]);
        }
        cpa_commit();
    };

    issue(0, 0); issue(32, 1);
    for (int i = 0; i < 8; i++) {
        if (i < 7) cpa_wait1(); else cpa_wait0();
        __syncthreads();
        if (i < 6) issue((i+2)*32, (i+2)%3);
        const float* sA = fs + (i%3)*STG;
        const float* sB = sA + ASZ;
        #pragma unroll
        for (int kc = 0; kc < 4; kc++) {
            unsigned a[MT][4], b[NT][2];
            #pragma unroll
            for (int mt = 0; mt < MT; mt++) {
                int r = wy*(16*MT) + mt*16 + g;
                a[mt][0] = F2U(sA[r*36 + kc*8 + t]);
                a[mt][1] = F2U(sA[(r+8)*36 + kc*8 + t]);
                a[mt][2] = F2U(sA[r*36 + kc*8 + t + 4]);
                a[mt][3] = F2U(sA[(r+8)*36 + kc*8 + t + 4]);
            }
            #pragma unroll
            for (int nt = 0; nt < NT; nt++) {
                int r = wx*(8*NT) + nt*8 + g;
                b[nt][0] = F2U(sB[r*36 + kc*8 + t]);
                b[nt][1] = F2U(sB[r*36 + kc*8 + t + 4]);
            }
            #pragma unroll
            for (int mt = 0; mt < MT; mt++)
                #pragma unroll
                for (int nt = 0; nt < NT; nt++)
                    mma8(acc[mt][nt], a[mt], b[nt]);
        }
        __syncthreads();
    }

    #pragma unroll
    for (int mt = 0; mt < MT; mt++) {
        #pragma unroll
        for (int nt = 0; nt < NT; nt++) {
            int row = m0 + wy*(16*MT) + mt*16 + g;
            int col = n0 + wx*(8*NT) + nt*8 + t*2;
            float2 bi = *(const float2*)&bias[col];
            float o00 = acc[mt][nt][0]+bi.x, o01 = acc[mt][nt][1]+bi.y;
            float o10 = acc[mt][nt][2]+bi.x, o11 = acc[mt][nt][3]+bi.y;
            if (resid) {
                float2 r0 = *(const float2*)&resid[(size_t)row*N + col];
                float2 r1 = *(const float2*)&resid[(size_t)(row+8)*N + col];
                o00 += r0.x; o01 += r0.y; o10 += r1.x; o11 += r1.y;
            }
            if (RND) { o00=tfr(o00); o01=tfr(o01); o10=tfr(o10); o11=tfr(o11); }
            *(float2*)&C[(size_t)row*N + col]     = make_float2(o00, o01);
            *(float2*)&C[(size_t)(row+8)*N + col] = make_float2(o10, o11);
        }
    }
}
#define GEMM_SMEM(MT,BN) (3*(((MT)*32+(BN))*36)*4)

// ---- dim_reduce fat-tile GEMM: CTA 128x256, warp tile 64x64 ----
// W read raw fp32, rounded at fragment load (no pre-round kernel needed)
#define DW_STG (32*132 + 256*36)
#define DIMW_SMEM_BYTES (3*DW_STG*4)
__global__ __launch_bounds__(256,1) void k_dimreduce_w(
    const float* __restrict__ feats, const float* __restrict__ W,
    const float* __restrict__ cb, const float* __restrict__ gamma,
    const float* __restrict__ beta, const float* __restrict__ mean,
    const float* __restrict__ var)
{
    extern __shared__ float fs[];
    unsigned sbase = smem_u32(fs);
    int m0 = blockIdx.y*128;
    int nb = m0 >> 4;
    int tid = threadIdx.x;
    int warp = tid >> 5, lane = tid & 31;
    int wy = warp >> 2, wx = warp & 3;
    int g = lane >> 2, t = lane & 3;
    float acc[4][8][4] = {};
    int lhw = (tid & 3)*4, lc = (tid >> 2) & 31, lnd = tid >> 7;
    int lr = tid >> 3, lkv = (tid & 7)*4;

    auto issue = [&](int k0, int st) {
        #pragma unroll
        for (int j = 0; j < 4; j++) {
            int nd = lnd + j*2;
            cpa16(sbase + (st*DW_STG + lc*132 + nd*16 + lhw)*4,
                  &feats[(size_t)(nb+nd)*4096 + (k0+lc)*16 + lhw]);
        }
        #pragma unroll
        for (int j = 0; j < 8; j++) {
            int r = lr + j*32;
            cpa16(sbase + (st*DW_STG + 4224 + r*36 + lkv)*4, &W[(size_t)r*256 + k0 + lkv]);
        }
        cpa_commit();
    };

    issue(0, 0); issue(32, 1);
    for (int i = 0; i < 8; i++) {
        if (i < 7) cpa_wait1(); else cpa_wait0();
        __syncthreads();
        if (i < 6) issue((i+2)*32, (i+2)%3);
        const float* sAT = fs + (i%3)*DW_STG;
        const float* sB  = sAT + 4224;
        #pragma unroll
        for (int kc = 0; kc < 4; kc++) {
            unsigned a[4][4], b[8][2];
            #pragma unroll
            for (int mt = 0; mt < 4; mt++) {
                int r = wy*64 + mt*16 + g;
                a[mt][0] = f2tf(sAT[(kc*8 + t)*132 + r]);
                a[mt][1] = f2tf(sAT[(kc*8 + t)*132 + r + 8]);
                a[mt][2] = f2tf(sAT[(kc*8 + t + 4)*132 + r]);
                a[mt][3] = f2tf(sAT[(kc*8 + t + 4)*132 + r + 8]);
            }
            #pragma unroll
            for (int nt = 0; nt < 8; nt++) {
                int r = wx*64 + nt*8 + g;
                b[nt][0] = f2tf(sB[r*36 + kc*8 + t]);
                b[nt][1] = f2tf(sB[r*36 + kc*8 + t + 4]);
            }
            #pragma unroll
            for (int mt = 0; mt < 4; mt++)
                #pragma unroll
                for (int nt = 0; nt < 8; nt++)
                    mma8(acc[mt][nt], a[mt], b[nt]);
        }
        __syncthreads();
    }
    #pragma unroll
    for (int mt = 0; mt < 4; mt++) {
        int node = nb + wy*4 + mt;
        #pragma unroll
        for (int nt = 0; nt < 8; nt++) {
            int col = wx*64 + nt*8 + t*2;
            float s0 = gamma[col]   * rsqrtf(var[col]   + 1e-5f);
            float s1 = gamma[col+1] * rsqrtf(var[col+1] + 1e-5f);
            float c0 = (cb[col]   - mean[col])  *s0 + beta[col];
            float c1 = (cb[col+1] - mean[col+1])*s1 + beta[col+1];
            float sum0 = fmaxf(acc[mt][nt][0]*s0 + c0, 0.f) + fmaxf(acc[mt][nt][2]*s0 + c0, 0.f);
            float sum1 = fmaxf(acc[mt][nt][1]*s1 + c1, 0.f) + fmaxf(acc[mt][nt][3]*s1 + c1, 0.f);
            #pragma unroll
            for (int msk = 4; msk < 32; msk <<= 1) {
                sum0 += __shfl_xor_sync(0xffffffffu, sum0, msk);
                sum1 += __shfl_xor_sync(0xffffffffu, sum1, msk);
            }
            if (g == 0) {
                d_x[node*HIDD + col]   = tfr(sum0 * (1.f/16.f));
                d_x[node*HIDD + col+1] = tfr(sum1 * (1.f/16.f));
            }
        }
    }
}

// ---- flash attention: q-tile 128, KV-tile 128 (two 64-key halves), 2-stage -
#define AQ   0
#define AKV  4608
#define ASTG 9216
#define ATT_SMEM_BYTES ((AKV + 2*ASTG)*4)

__global__ __launch_bounds__(256,2) void k_attn_t(const float* __restrict__ qkv,
                                                  float* __restrict__ out)
{
    extern __shared__ float fs[];
    unsigned sbase = smem_u32(fs);
    int h  = blockIdx.y;
    int q0 = blockIdx.x * 128;
    int tid = threadIdx.x;
    int warp = tid >> 5, lane = tid & 31;
    int g = lane >> 2, t = lane & 3;
    const float scale = 0.17677669529663689f;   // 32^-0.5
    int lr = tid >> 3, lkv = (tid & 7)*4;
    int qr = warp*16 + g;

    #pragma unroll
    for (int j = 0; j < 4; j++) {
        int r = lr + j*32;
        float4 v = *(const float4*)&qkv[(size_t)(q0+r)*768 + h*32 + lkv];
        float* p = &fs[AQ + r*36 + lkv];
        p[0]=tfr(v.x*scale); p[1]=tfr(v.y*scale);
        p[2]=tfr(v.z*scale); p[3]=tfr(v.w*scale);
    }

    auto issue = [&](int kt) {
        unsigned kb = sbase + (AKV + (kt&1)*ASTG)*4;
        #pragma unroll
        for (int j = 0; j < 4; j++) {
            int r = lr + j*32;
            int pr = (r & ~7) | (((r & 3) << 1) | ((r >> 2) & 1));  // K row permute
            const float* srcK = &qkv[(size_t)(kt*128+r)*768 + 256 + h*32 + lkv];
            cpa16(kb + (pr*36 + lkv)*4,          srcK);
            cpa16(kb + ((4608 + r*36) + lkv)*4,  srcK + 256);
        }
        cpa_commit();
    };

    issue(0);
    __syncthreads();

    unsigned qa[4][4];
    #pragma unroll
    for (int kc = 0; kc < 4; kc++) {
        qa[kc][0] = F2U(fs[AQ + qr*36 + kc*8 + t]);
        qa[kc][1] = F2U(fs[AQ + (qr+8)*36 + kc*8 + t]);
        qa[kc][2] = F2U(fs[AQ + qr*36 + kc*8 + t + 4]);
        qa[kc][3] = F2U(fs[AQ + (qr+8)*36 + kc*8 + t + 4]);
    }

    float l0 = 0.f, l1 = 0.f;
    float o[4][4] = {};

    for (int it = 0; it < 32; it++) {
        cpa_wait0();
        __syncthreads();
        if (it < 31) issue(it+1);
        const float* sKt = fs + AKV + (it&1)*ASTG;

        #pragma unroll
        for (int half = 0; half < 2; half++) {
            const float* sK = sKt + half*64*36;
            const float* sV = sKt + 4608 + half*64*36;

            float s[8][4] = {};
            #pragma unroll
            for (int kc = 0; kc < 4; kc++) {
                unsigned b[8][2];
                #pragma unroll
                for (int nt = 0; nt < 8; nt++) {
                    b[nt][0] = F2U(sK[(nt*8+g)*36 + kc*8 + t]);
                    b[nt][1] = F2U(sK[(nt*8+g)*36 + kc*8 + t + 4]);
                }
                #pragma unroll
                for (int nt = 0; nt < 8; nt++) mma8(s[nt], qa[kc], b[nt]);
            }

            #pragma unroll
            for (int nt = 0; nt < 8; nt++) {
                float e0 = __expf(s[nt][0]); l0 += e0; s[nt][0] = __uint_as_float(f2tf(e0));
                float e1 = __expf(s[nt][1]); l0 += e1; s[nt][1] = __uint_as_float(f2tf(e1));
                float e2 = __expf(s[nt][2]); l1 += e2; s[nt][2] = __uint_as_float(f2tf(e2));
                float e3 = __expf(s[nt][3]); l1 += e3; s[nt][3] = __uint_as_float(f2tf(e3));
            }

            #pragma unroll
            for (int kc = 0; kc < 8; kc++) {
                unsigned a[4] = { F2U(s[kc][0]), F2U(s[kc][2]), F2U(s[kc][1]), F2U(s[kc][3]) };
                unsigned b[4][2];
                #pragma unroll
                for (int dt = 0; dt < 4; dt++) {
                    b[dt][0] = F2U(sV[(kc*8 + t)*36 + dt*8 + g]);
                    b[dt][1] = F2U(sV[(kc*8 + t + 4)*36 + dt*8 + g]);
                }
                #pragma unroll
                for (int dt = 0; dt < 4; dt++) mma8(o[dt], a, b[dt]);
            }
        }
    }

    #pragma unroll
    for (int msk = 1; msk < 4; msk <<= 1) {
        l0 += __shfl_xor_sync(0xffffffffu, l0, msk);
        l1 += __shfl_xor_sync(0xffffffffu, l1, msk);
    }
    float inv0 = 1.f / l0, inv1 = 1.f / l1;
    int r = q0 + qr;
    #pragma unroll
    for (int dt = 0; dt < 4; dt++) {
        int col = h*32 + dt*8 + t*2;
        *(float2*)&out[(size_t)r*256 + col]     = make_float2(tfr(o[dt][0]*inv0), tfr(o[dt][1]*inv0));
        *(float2*)&out[(size_t)(r+8)*256 + col] = make_float2(tfr(o[dt][2]*inv1), tfr(o[dt][3]*inv1));
    }
}

// ---- graph ----
__global__ void k_deg(const void* __restrict__ edges, const float* __restrict__ ew) {
    int e = blockIdx.x*blockDim.x + threadIdx.x;
    if (e >= NEDGE) return;
    int r, c; get_edge(edges, e, r, c);
    float w = ew[e];
    atomicAdd(&d_deg[r], w);  atomicAdd(&d_deg[c], w);
    atomicAdd(&d_rowcnt[r], 1); atomicAdd(&d_rowcnt[c], 1);
}
__global__ __launch_bounds__(1024) void k_scan() {
    __shared__ int s[1024];
    int tid = threadIdx.x;
    #pragma unroll
    for (int j = 0; j < 4; j++) {
        int i = tid*4 + j;
        d_dinv[i] = rsqrtf(d_deg[i] + 1e-6f);
    }
    int c0 = d_rowcnt[tid*4], c1 = d_rowcnt[tid*4+1], c2 = d_rowcnt[tid*4+2], c3 = d_rowcnt[tid*4+3];
    int p0 = c0, p1 = p0+c1, p2 = p1+c2, p3 = p2+c3;
    s[tid] = p3;
    __syncthreads();
    for (int off = 1; off < 1024; off <<= 1) {
        int v = (tid >= off) ? s[tid-off] : 0;
        __syncthreads(); s[tid] += v; __syncthreads();
    }
    int excl = s[tid] - p3;
    d_rowptr[tid*4] = excl; d_rowptr[tid*4+1] = excl+p0;
    d_rowptr[tid*4+2] = excl+p1; d_rowptr[tid*4+3] = excl+p2;
    if (tid == 1023) d_rowptr[NNODES] = s[1023];
}
__global__ void k_fill(const void* __restrict__ edges, const float* __restrict__ ew) {
    int e = blockIdx.x*blockDim.x + threadIdx.x;
    if (e >= NEDGE) return;
    int r, c; get_edge(edges, e, r, c);
    float w = ew[e];
    int p1 = d_rowptr[r] + atomicAdd(&d_fillcnt[r], 1);
    d_col[p1] = c;  d_coef[p1] = w * d_dinv[c];
    int p2 = d_rowptr[c] + atomicAdd(&d_fillcnt[c], 1);
    d_col[p2] = r;  d_coef[p2] = w * d_dinv[r];
}

// ---- SpMM with fused bias + LayerNorm + ReLU (+resid add, post-relu) ------
// one node per block, F threads. FIN=true: round output to tf32 (feeds GEMMs).
template<int F, bool RESID>
__global__ __launch_bounds__(F) void k_spmm_ln(
    const float* __restrict__ xin, const float* __restrict__ bias,
    const float* __restrict__ lnG, const float* __restrict__ lnB,
    const float* __restrict__ resid, float* __restrict__ xout)
{
    int n = blockIdx.x, t = threadIdx.x;
    int s = d_rowptr[n], e = d_rowptr[n+1];
    float a0 = 0.f, a1 = 0.f, a2 = 0.f, a3 = 0.f;
    int j = s;
    for (; j + 4 <= e; j += 4) {
        int   c0 = __ldg(&d_col[j]),   c1 = __ldg(&d_col[j+1]);
        int   c2 = __ldg(&d_col[j+2]), c3 = __ldg(&d_col[j+3]);
        float f0 = __ldg(&d_coef[j]),  f1 = __ldg(&d_coef[j+1]);
        float f2 = __ldg(&d_coef[j+2]),f3 = __ldg(&d_coef[j+3]);
        a0 += f0 * xin[(size_t)c0*F + t];
        a1 += f1 * xin[(size_t)c1*F + t];
        a2 += f2 * xin[(size_t)c2*F + t];
        a3 += f3 * xin[(size_t)c3*F + t];
    }
    for (; j < e; j++)
        a0 += __ldg(&d_coef[j]) * xin[(size_t)__ldg(&d_col[j])*F + t];
    float v = d_dinv[n] * ((a0+a1)+(a2+a3)) + bias[t];

    // LayerNorm over F
    float s1 = v, s2 = v*v;
    #pragma unroll
    for (int msk = 16; msk; msk >>= 1) {
        s1 += __shfl_xor_sync(0xffffffffu, s1, msk);
        s2 += __shfl_xor_sync(0xffffffffu, s2, msk);
    }
    __shared__ float w1[F/32], w2[F/32];
    int wid = t >> 5, lid = t & 31;
    if (lid == 0) { w1[wid] = s1; w2[wid] = s2; }
    __syncthreads();
    float ts1 = 0.f, ts2 = 0.f;
    #pragma unroll
    for (int i = 0; i < F/32; i++) { ts1 += w1[i]; ts2 += w2[i]; }
    float mu = ts1 / F;
    float r = rsqrtf(ts2/F - mu*mu + 1e-5f);
    float res = fmaxf((v - mu)*r*lnG[t] + lnB[t], 0.f);
    if (RESID) {
        res += resid[(size_t)n*F + t];
        xout[(size_t)n*F + t] = res;          // final output: no rounding
    } else {
        xout[(size_t)n*F + t] = tfr(res);     // feeds GEMMs: tf32
    }
}

extern "C" void kernel_launch(void* const* d_in, const int* in_sizes, int n_in,
                              void* d_out, int out_size) {
    const float* node_feats = (const float*)d_in[0];
    const void*  edges      = d_in[1];
    const float* ew         = (const float*)d_in[2];
    const float* conv_w  = (const float*)d_in[3];
    const float* conv_b  = (const float*)d_in[4];
    const float* bn_g    = (const float*)d_in[5];
    const float* bn_b    = (const float*)d_in[6];
    const float* bn_m    = (const float*)d_in[7];
    const float* bn_v    = (const float*)d_in[8];
    const float* qkv_b   = (const float*)d_in[10];
    const float* proj_b  = (const float*)d_in[12];
    const float* gcn1_b  = (const float*)d_in[14];
    const float* ln1_g   = (const float*)d_in[15];
    const float* ln1_b   = (const float*)d_in[16];
    const float* gcn2_b  = (const float*)d_in[18];
    const float* ln2_g   = (const float*)d_in[19];
    const float* ln2_b   = (const float*)d_in[20];
    const float* sc_b    = (const float*)d_in[22];
    float* out = (float*)d_out;

    float *p_x,*p_qkv,*p_att,*p_x2,*p_s1,*p_g1,*p_s2,*p_zero;
    float *p_wq,*p_wp,*p_w1,*p_w2,*p_ws;
    cudaGetSymbolAddress((void**)&p_x, d_x);   cudaGetSymbolAddress((void**)&p_qkv, d_qkv);
    cudaGetSymbolAddress((void**)&p_att, d_att); cudaGetSymbolAddress((void**)&p_x2, d_x2);
    cudaGetSymbolAddress((void**)&p_s1, d_s1); cudaGetSymbolAddress((void**)&p_g1, d_g1);
    cudaGetSymbolAddress((void**)&p_s2, d_s2); cudaGetSymbolAddress((void**)&p_zero, d_zero);
    cudaGetSymbolAddress((void**)&p_wq, d_wq); cudaGetSymbolAddress((void**)&p_wp, d_wp);
    cudaGetSymbolAddress((void**)&p_w1, d_w1); cudaGetSymbolAddress((void**)&p_w2, d_w2);
    cudaGetSymbolAddress((void**)&p_ws, d_ws);

    static cudaStream_t s1;
    static cudaEvent_t evF1, evJ1, evF2, evJ2, evW;
    static int done = 0;
    if (!done) {
        cudaFuncSetAttribute((const void*)k_gemm_t<4,128,true>,  cudaFuncAttributeMaxDynamicSharedMemorySize, GEMM_SMEM(4,128));
        cudaFuncSetAttribute((const void*)k_gemm_t<2,128,false>, cudaFuncAttributeMaxDynamicSharedMemorySize, GEMM_SMEM(2,128));
        cudaFuncSetAttribute((const void*)k_gemm_t<1,128,false>, cudaFuncAttributeMaxDynamicSharedMemorySize, GEMM_SMEM(1,128));
        cudaFuncSetAttribute(k_dimreduce_w, cudaFuncAttributeMaxDynamicSharedMemorySize, DIMW_SMEM_BYTES);
        cudaFuncSetAttribute(k_attn_t,      cudaFuncAttributeMaxDynamicSharedMemorySize, ATT_SMEM_BYTES);
        cudaStreamCreateWithFlags(&s1, cudaStreamNonBlocking);
        cudaEventCreateWithFlags(&evF1, cudaEventDisableTiming);
        cudaEventCreateWithFlags(&evJ1, cudaEventDisableTiming);
        cudaEventCreateWithFlags(&evF2, cudaEventDisableTiming);
        cudaEventCreateWithFlags(&evJ2, cudaEventDisableTiming);
        cudaEventCreateWithFlags(&evW,  cudaEventDisableTiming);
        done = 1;
    }

    // ---- fork: weight rounding + graph-structure chain on side stream ----
    cudaEventRecord(evF1, 0);
    cudaStreamWaitEvent(s1, evF1, 0);
    k_round_rest<<<(RR_TOT+255)/256, 256, 0, s1>>>((const float*)d_in[9], (const float*)d_in[11],
        (const float*)d_in[13], (const float*)d_in[17], (const float*)d_in[21]);
    cudaEventRecord(evW, s1);
    k_init<<<16, 256, 0, s1>>>((const int*)edges);
    k_deg <<<NEDGE/256, 256, 0, s1>>>(edges, ew);
    k_scan<<<1, 1024, 0, s1>>>();
    k_fill<<<NEDGE/256, 256, 0, s1>>>(edges, ew);
    cudaEventRecord(evJ1, s1);

    // ---- main chain ----
    k_dimreduce_w<<<dim3(1, 512), 256, DIMW_SMEM_BYTES>>>(node_feats, conv_w, conv_b, bn_g, bn_b, bn_m, bn_v);

    cudaStreamWaitEvent(0, evW, 0);
    k_gemm_t<4,128,true><<<dim3(6, 32), 256, GEMM_SMEM(4,128)>>>(
        p_x, p_wq, qkv_b, nullptr, p_qkv, 768);

    k_attn_t<<<dim3(32, NHEADS), 256, ATT_SMEM_BYTES>>>(p_qkv, p_att);

    k_gemm_t<2,128,false><<<dim3(2, 64), 256, GEMM_SMEM(2,128)>>>(
        p_att, p_wp, proj_b, nullptr, p_x2, 256);

    // gcn1 reassociated: y1 = x2 @ W1^T (no graph needed yet)
    k_gemm_t<2,128,false><<<dim3(2, 64), 256, GEMM_SMEM(2,128)>>>(
        p_x2, p_w1, p_zero, nullptr, p_s1, 256);

    cudaStreamWaitEvent(0, evJ1, 0);  // graph structure ready
    // g1 = relu(LN(spmm(y1) + b1)), tf32-rounded
    k_spmm_ln<256,false><<<NNODES, 256>>>(p_s1, gcn1_b, ln1_g, ln1_b, nullptr, p_g1);

    // ---- fork: shortcut GEMM on side stream, y2 GEMM on main (concurrent) --
    cudaEventRecord(evF2, 0);
    cudaStreamWaitEvent(s1, evF2, 0);
    k_gemm_t<1,128,false><<<dim3(1, 128), 256, GEMM_SMEM(1,128), s1>>>(
        p_g1, p_ws, sc_b, nullptr, out, 128);
    cudaEventRecord(evJ2, s1);

    // y2 = g1 @ W2^T (128-wide)
    k_gemm_t<1,128,false><<<dim3(1, 128), 256, GEMM_SMEM(1,128)>>>(
        p_g1, p_w2, p_zero, nullptr, p_s2, 128);

    cudaStreamWaitEvent(0, evJ2, 0);
    // out = relu(LN(spmm(y2) + b2)) + shortcut   (spmm on 128 features)
    k_spmm_ln<128,true><<<NNODES, 128>>>(p_s2, gcn2_b, ln2_g, ln2_b, out, out);
}